// round 3
// baseline (speedup 1.0000x reference)
#include <cuda_runtime.h>
#include <math.h>

#define NN   50000
#define EE   800000
#define IN_C 128
#define HID  256
#define EMBD 128
#define RR   4
#define NBLK ((NN + 255) / 256)   // 196 scan blocks

// ---------------- scratch (device globals; no allocation) ----------------
__device__ int      g_deg[NN];
__device__ float    g_invdeg[NN];
__device__ int      g_cnt4[NN * RR];
__device__ float    g_invcnt4[NN * RR];
__device__ int      g_rowstart[NN];
__device__ int      g_cursor[NN];
__device__ int      g_bsum[256];
__device__ int      g_boff[256];
__device__ int      g_es[EE];       // CSR: src per slot (sorted by dst)
__device__ int      g_etl[EE];      // CSR: edge type per slot
__device__ float    g_agg1[(size_t)NN * IN_C];
__device__ float    g_x1[(size_t)NN * HID];
__device__ float    g_agg2[(size_t)NN * HID];
__device__ float    g_xsage[(size_t)NN * HID];
__device__ float    g_h[(size_t)NN * 2 * HID];
__device__ float    g_als[NN * 2];
__device__ float    g_ald[NN * 2];
__device__ float    g_xgat[(size_t)NN * HID];
__device__ float    g_xt[(size_t)RR * NN * EMBD];
__device__ float    g_xrgcn[(size_t)NN * EMBD];

__device__ __forceinline__ float lrelu(float v) { return v > 0.f ? v : 0.2f * v; }

// packed fp32x2 FMA (FFMA2) — only reachable via PTX on sm_103a
#define FMA_F32X2(d, a, b, c) \
    asm("fma.rn.f32x2 %0, %1, %2, %3;" : "=l"(d) : "l"(a), "l"(b), "l"(c))

__device__ __forceinline__ float2 unpack_f32x2(unsigned long long v) {
    float2 f;
    f.x = __uint_as_float((unsigned)(v & 0xffffffffull));
    f.y = __uint_as_float((unsigned)(v >> 32));
    return f;
}

// ---------------- zero / counts ----------------
__global__ void k_zero_small() {
    int i = blockIdx.x * blockDim.x + threadIdx.x;
    if (i < NN) { g_deg[i] = 0; g_cursor[i] = 0; }
    if (i < NN * RR) g_cnt4[i] = 0;
}

__global__ void k_count(const int* __restrict__ dst, const int* __restrict__ et) {
    int i = blockIdx.x * blockDim.x + threadIdx.x;
    if (i >= EE) return;
    int d = dst[i];
    atomicAdd(&g_deg[d], 1);
    atomicAdd(&g_cnt4[d * RR + et[i]], 1);
}

__global__ void k_inv() {
    int i = blockIdx.x * blockDim.x + threadIdx.x;
    if (i >= NN) return;
    g_invdeg[i] = 1.f / fmaxf((float)g_deg[i], 1.f);
#pragma unroll
    for (int r = 0; r < RR; r++)
        g_invcnt4[i * RR + r] = 1.f / fmaxf((float)g_cnt4[i * RR + r], 1.f);
}

// ---------------- 3-kernel exclusive scan of g_deg -> g_rowstart ----------------
__global__ void k_scan1() {
    __shared__ int sh[256];
    int b = blockIdx.x, t = threadIdx.x;
    int i = b * 256 + t;
    int v = (i < NN) ? g_deg[i] : 0;
    sh[t] = v; __syncthreads();
    for (int o = 1; o < 256; o <<= 1) {
        int add = (t >= o) ? sh[t - o] : 0;
        __syncthreads();
        sh[t] += add;
        __syncthreads();
    }
    if (i < NN) g_rowstart[i] = sh[t] - v;
    if (t == 255) g_bsum[b] = sh[255];
}

__global__ void k_scan2() {
    __shared__ int sh[256];
    int t = threadIdx.x;
    int v = (t < NBLK) ? g_bsum[t] : 0;
    sh[t] = v; __syncthreads();
    for (int o = 1; o < 256; o <<= 1) {
        int add = (t >= o) ? sh[t - o] : 0;
        __syncthreads();
        sh[t] += add;
        __syncthreads();
    }
    g_boff[t] = sh[t] - v;
}

__global__ void k_scan3() {
    int i = blockIdx.x * blockDim.x + threadIdx.x;
    if (i < NN) g_rowstart[i] += g_boff[i >> 8];
}

__global__ void k_fill(const int* __restrict__ src, const int* __restrict__ dst,
                       const int* __restrict__ et) {
    int e = blockIdx.x * blockDim.x + threadIdx.x;
    if (e >= EE) return;
    int d = dst[e];
    int pos = atomicAdd(&g_cursor[d], 1);
    int slot = g_rowstart[d] + pos;
    g_es[slot] = src[e];
    g_etl[slot] = et[e];
}

// ---------------- SAGE mean-gather: one block per node, one thread per column ----------------
template <int D>
__global__ __launch_bounds__(D) void k_sage_gather(const float* __restrict__ xin,
                                                   float* __restrict__ agg) {
    int n = blockIdx.x;
    int c = threadIdx.x;
    int base = g_rowstart[n], deg = g_deg[n];
    const int* es = g_es + base;
    float acc = 0.f;
    int j = 0;
    for (; j + 4 <= deg; j += 4) {
        int s0 = es[j], s1 = es[j + 1], s2 = es[j + 2], s3 = es[j + 3];
        float v0 = xin[(size_t)s0 * D + c];
        float v1 = xin[(size_t)s1 * D + c];
        float v2 = xin[(size_t)s2 * D + c];
        float v3 = xin[(size_t)s3 * D + c];
        acc += (v0 + v1) + (v2 + v3);
    }
    for (; j < deg; j++) acc += xin[(size_t)es[j] * D + c];
    agg[(size_t)n * D + c] = acc * g_invdeg[n];
}

// ---------------- 128x128x8 SGEMM, 8x8 microtile, packed f32x2 FMA ----------------
// A duplicated in shared ({a,a} pairs) so LDS.128 yields two broadcast pairs.
__global__ __launch_bounds__(256) void sgemm(
    const float* __restrict__ A, const float* __restrict__ B, float* __restrict__ C,
    const float* __restrict__ bias,
    int M, int Nc, int K, int accFlag, int reluFlag) {
    __shared__ float As2[8][256];   // duplicated: As2[k][2m] = As2[k][2m+1] = A[m][k]
    __shared__ float Bs[8][128];
    int tid = threadIdx.x;
    int m0 = blockIdx.y * 128;
    int n0 = blockIdx.x * 128;

    int aRow = tid >> 1;
    int aCol = (tid & 1) * 4;
    int bRow = tid >> 5;
    int bCol = (tid & 31) * 4;

    bool aValid = (m0 + aRow) < M;
    const float* Aptr = A + (size_t)(m0 + aRow) * K + aCol;
    const float* Bptr = B + (size_t)bRow * Nc + n0 + bCol;

    int tx = tid & 15, ty = tid >> 4;
    unsigned long long acc2[8][4];
#pragma unroll
    for (int i = 0; i < 8; i++)
#pragma unroll
        for (int j = 0; j < 4; j++) acc2[i][j] = 0ull;

    for (int k0 = 0; k0 < K; k0 += 8) {
        float4 av = aValid ? *(const float4*)(Aptr + k0) : make_float4(0.f, 0.f, 0.f, 0.f);
        float4 bv = *(const float4*)(Bptr + (size_t)k0 * Nc);
        *(float2*)&As2[aCol + 0][2 * aRow] = make_float2(av.x, av.x);
        *(float2*)&As2[aCol + 1][2 * aRow] = make_float2(av.y, av.y);
        *(float2*)&As2[aCol + 2][2 * aRow] = make_float2(av.z, av.z);
        *(float2*)&As2[aCol + 3][2 * aRow] = make_float2(av.w, av.w);
        *(float4*)&Bs[bRow][bCol] = bv;
        __syncthreads();
#pragma unroll
        for (int kk = 0; kk < 8; kk++) {
            unsigned long long ra2[8], rb2[4];
#pragma unroll
            for (int i = 0; i < 8; i += 2) {
                ulonglong2 t2 = *(const ulonglong2*)&As2[kk][(ty * 8 + i) * 2];
                ra2[i] = t2.x; ra2[i + 1] = t2.y;
            }
#pragma unroll
            for (int j = 0; j < 2; j++) {
                ulonglong2 t2 = *(const ulonglong2*)&Bs[kk][tx * 8 + 4 * j];
                rb2[2 * j] = t2.x; rb2[2 * j + 1] = t2.y;
            }
#pragma unroll
            for (int i = 0; i < 8; i++)
#pragma unroll
                for (int j2 = 0; j2 < 4; j2++)
                    FMA_F32X2(acc2[i][j2], ra2[i], rb2[j2], acc2[i][j2]);
        }
        __syncthreads();
    }

#pragma unroll
    for (int i = 0; i < 8; i++) {
        int row = m0 + ty * 8 + i;
        if (row >= M) continue;
        float* cp = C + (size_t)row * Nc + n0 + tx * 8;
#pragma unroll
        for (int j4 = 0; j4 < 2; j4++) {
            float* p = cp + j4 * 4;
            float2 lo = unpack_f32x2(acc2[i][j4 * 2 + 0]);
            float2 hi = unpack_f32x2(acc2[i][j4 * 2 + 1]);
            float4 old = accFlag ? *(const float4*)p : make_float4(0.f, 0.f, 0.f, 0.f);
            float4 cv;
            cv.x = lo.x + old.x;
            cv.y = lo.y + old.y;
            cv.z = hi.x + old.z;
            cv.w = hi.y + old.w;
            if (bias != nullptr) {
                const float* bp = bias + n0 + tx * 8 + j4 * 4;
                cv.x += bp[0]; cv.y += bp[1]; cv.z += bp[2]; cv.w += bp[3];
            }
            if (reluFlag) {
                cv.x = fmaxf(cv.x, 0.f); cv.y = fmaxf(cv.y, 0.f);
                cv.z = fmaxf(cv.z, 0.f); cv.w = fmaxf(cv.w, 0.f);
            }
            *(float4*)p = cv;
        }
    }
}

// ---------------- GAT: per-node attention logits ----------------
__global__ __launch_bounds__(256) void k_al(const float* __restrict__ aS,
                                            const float* __restrict__ aD) {
    int gw = (int)(((size_t)blockIdx.x * blockDim.x + threadIdx.x) >> 5);
    int lane = threadIdx.x & 31;
    if (gw >= NN * 2) return;
    int n = gw >> 1, k = gw & 1;
    const float* hp = g_h + (size_t)n * 512 + k * 256;
    const float* as = aS + k * 256;
    const float* ad = aD + k * 256;
    float ss = 0.f, sd = 0.f;
    for (int d2 = lane; d2 < 256; d2 += 32) {
        float hv = hp[d2];
        ss += hv * as[d2];
        sd += hv * ad[d2];
    }
#pragma unroll
    for (int o = 16; o; o >>= 1) {
        ss += __shfl_down_sync(0xffffffffu, ss, o);
        sd += __shfl_down_sync(0xffffffffu, sd, o);
    }
    if (lane == 0) { g_als[gw] = ss; g_ald[gw] = sd; }
}

// ---------------- GAT: fused softmax + weighted gather, one block per node ----------------
__global__ __launch_bounds__(256) void k_gat(const float* __restrict__ bias) {
    __shared__ float sAl0[256], sAl1[256];
    __shared__ int   sS[256];
    __shared__ float red[256];
    int n = blockIdx.x;
    int t = threadIdx.x;
    int base = g_rowstart[n], deg = g_deg[n];

    float ald0 = g_ald[2 * n], ald1 = g_ald[2 * n + 1];
    float selfE0 = lrelu(g_als[2 * n] + ald0);
    float selfE1 = lrelu(g_als[2 * n + 1] + ald1);

    // pass A: per-head max over edges + self loop
    float m0 = selfE0, m1 = selfE1;
    for (int j = t; j < deg; j += 256) {
        int s = g_es[base + j];
        m0 = fmaxf(m0, lrelu(g_als[2 * s] + ald0));
        m1 = fmaxf(m1, lrelu(g_als[2 * s + 1] + ald1));
    }
    red[t] = m0; __syncthreads();
    for (int o = 128; o; o >>= 1) { if (t < o) red[t] = fmaxf(red[t], red[t + o]); __syncthreads(); }
    m0 = red[0]; __syncthreads();
    red[t] = m1; __syncthreads();
    for (int o = 128; o; o >>= 1) { if (t < o) red[t] = fmaxf(red[t], red[t + o]); __syncthreads(); }
    m1 = red[0]; __syncthreads();

    // pass B: denominator
    float d0 = (t == 0) ? expf(selfE0 - m0) : 0.f;
    float d1 = (t == 0) ? expf(selfE1 - m1) : 0.f;
    for (int j = t; j < deg; j += 256) {
        int s = g_es[base + j];
        d0 += expf(lrelu(g_als[2 * s] + ald0) - m0);
        d1 += expf(lrelu(g_als[2 * s + 1] + ald1) - m1);
    }
    red[t] = d0; __syncthreads();
    for (int o = 128; o; o >>= 1) { if (t < o) red[t] += red[t + o]; __syncthreads(); }
    d0 = red[0]; __syncthreads();
    red[t] = d1; __syncthreads();
    for (int o = 128; o; o >>= 1) { if (t < o) red[t] += red[t + o]; __syncthreads(); }
    d1 = red[0]; __syncthreads();
    float inv0 = 1.f / fmaxf(d0, 1e-16f);
    float inv1 = 1.f / fmaxf(d1, 1e-16f);

    // pass C: weighted gather (self loop + chunked edge list)
    const float* hn = g_h + (size_t)n * 512;
    float a0 = expf(selfE0 - m0) * inv0 * hn[t];
    float a1 = expf(selfE1 - m1) * inv1 * hn[256 + t];
    for (int c0 = 0; c0 < deg; c0 += 256) {
        int cnt = min(256, deg - c0);
        if (t < cnt) {
            int s = g_es[base + c0 + t];
            sS[t] = s;
            sAl0[t] = expf(lrelu(g_als[2 * s] + ald0) - m0) * inv0;
            sAl1[t] = expf(lrelu(g_als[2 * s + 1] + ald1) - m1) * inv1;
        }
        __syncthreads();
        for (int j = 0; j < cnt; j++) {
            const float* hs = g_h + (size_t)sS[j] * 512;
            a0 += sAl0[j] * hs[t];
            a1 += sAl1[j] * hs[256 + t];
        }
        __syncthreads();
    }
    float v = 0.5f * (a0 + a1) + bias[t];
    g_xgat[(size_t)n * 256 + t] = fmaxf(v, 0.f);
}

// ---------------- RGCN gather: per-relation mean folded into per-edge weight ----------------
__global__ __launch_bounds__(128) void k_rgcn() {
    int n = blockIdx.x;
    int c = threadIdx.x;
    int base = g_rowstart[n], deg = g_deg[n];
    float w0 = g_invcnt4[n * 4 + 0], w1 = g_invcnt4[n * 4 + 1];
    float w2 = g_invcnt4[n * 4 + 2], w3 = g_invcnt4[n * 4 + 3];
    float acc = 0.f;
#pragma unroll 2
    for (int j = 0; j < deg; j++) {
        int s = g_es[base + j];
        int r = g_etl[base + j];
        float w = (r == 0) ? w0 : (r == 1) ? w1 : (r == 2) ? w2 : w3;
        acc += w * g_xt[((size_t)r * NN + s) * EMBD + c];
    }
    g_xrgcn[(size_t)n * EMBD + c] = acc;
}

// ---------------- final L2 normalize ----------------
__global__ void k_norm(float* __restrict__ out) {
    int n = blockIdx.x;
    int t = threadIdx.x;   // 128 threads
    float v = out[(size_t)n * EMBD + t];
    float s = v * v;
#pragma unroll
    for (int o = 16; o; o >>= 1) s += __shfl_down_sync(0xffffffffu, s, o);
    __shared__ float sh[4];
    if ((t & 31) == 0) sh[t >> 5] = s;
    __syncthreads();
    float tot = sh[0] + sh[1] + sh[2] + sh[3];
    float nrm = fmaxf(sqrtf(tot), 1e-12f);
    out[(size_t)n * EMBD + t] = v / nrm;
}

// ---------------- host ----------------
static void launch_gemm(const float* A, const float* B, float* C, const float* bias,
                        int M, int Nc, int K, int acc, int relu) {
    dim3 grid(Nc / 128, (M + 127) / 128);
    sgemm<<<grid, 256>>>(A, B, C, bias, M, Nc, K, acc, relu);
}

extern "C" void kernel_launch(void* const* d_in, const int* in_sizes, int n_in,
                              void* d_out, int out_size) {
    const float* x    = (const float*)d_in[0];
    const int*   ei   = (const int*)d_in[1];
    const int*   et   = (const int*)d_in[2];
    const float* s1Wl = (const float*)d_in[3];
    const float* s1Wr = (const float*)d_in[4];
    const float* s1b  = (const float*)d_in[5];
    const float* s2Wl = (const float*)d_in[6];
    const float* s2Wr = (const float*)d_in[7];
    const float* s2b  = (const float*)d_in[8];
    const float* gatW = (const float*)d_in[9];
    const float* aSrc = (const float*)d_in[10];
    const float* aDst = (const float*)d_in[11];
    const float* gatB = (const float*)d_in[12];
    const float* Wrel = (const float*)d_in[13];
    const float* Wroot= (const float*)d_in[14];
    const float* rgcB = (const float*)d_in[15];
    const float* fW   = (const float*)d_in[16];
    const float* fB   = (const float*)d_in[17];
    float* out = (float*)d_out;

    const int* src = ei;
    const int* dst = ei + EE;

    float *p_agg1, *p_x1, *p_agg2, *p_xsage, *p_h, *p_xgat, *p_xt, *p_xrgcn;
    cudaGetSymbolAddress((void**)&p_agg1, g_agg1);
    cudaGetSymbolAddress((void**)&p_x1, g_x1);
    cudaGetSymbolAddress((void**)&p_agg2, g_agg2);
    cudaGetSymbolAddress((void**)&p_xsage, g_xsage);
    cudaGetSymbolAddress((void**)&p_h, g_h);
    cudaGetSymbolAddress((void**)&p_xgat, g_xgat);
    cudaGetSymbolAddress((void**)&p_xt, g_xt);
    cudaGetSymbolAddress((void**)&p_xrgcn, g_xrgcn);

    // ---- CSR build ----
    k_zero_small<<<(NN * RR + 255) / 256, 256>>>();
    k_count<<<(EE + 255) / 256, 256>>>(dst, et);
    k_inv<<<(NN + 255) / 256, 256>>>();
    k_scan1<<<NBLK, 256>>>();
    k_scan2<<<1, 256>>>();
    k_scan3<<<NBLK, 256>>>();
    k_fill<<<(EE + 255) / 256, 256>>>(src, dst, et);

    // ---- SAGE 1 ----
    k_sage_gather<IN_C><<<NN, IN_C>>>(x, p_agg1);
    launch_gemm(x, s1Wr, p_x1, nullptr, NN, HID, IN_C, 0, 0);
    launch_gemm(p_agg1, s1Wl, p_x1, s1b, NN, HID, IN_C, 1, 1);

    // ---- SAGE 2 ----
    k_sage_gather<HID><<<NN, HID>>>(p_x1, p_agg2);
    launch_gemm(p_x1, s2Wr, p_xsage, nullptr, NN, HID, HID, 0, 0);
    launch_gemm(p_agg2, s2Wl, p_xsage, s2b, NN, HID, HID, 1, 1);

    // ---- GAT ----
    launch_gemm(p_xsage, gatW, p_h, nullptr, NN, 2 * HID, HID, 0, 0);
    k_al<<<(NN * 2 * 32 + 255) / 256, 256>>>(aSrc, aDst);
    k_gat<<<NN, 256>>>(gatB);

    // ---- RGCN ----
    for (int r = 0; r < RR; r++)
        launch_gemm(p_xgat, Wrel + (size_t)r * HID * EMBD, p_xt + (size_t)r * NN * EMBD,
                    nullptr, NN, EMBD, HID, 0, 0);
    k_rgcn<<<NN, 128>>>();
    launch_gemm(p_xgat, Wroot, p_xrgcn, rgcB, NN, EMBD, HID, 1, 0);

    // ---- Fusion + normalize ----
    launch_gemm(p_xsage, fW,              out, nullptr, NN, EMBD, HID, 0, 0);
    launch_gemm(p_xgat,  fW + 256 * EMBD, out, nullptr, NN, EMBD, HID, 1, 0);
    launch_gemm(p_xrgcn, fW + 512 * EMBD, out, fB,      NN, EMBD, EMBD, 1, 0);
    k_norm<<<NN, 128>>>(out);
}

// round 4
// speedup vs baseline: 1.7692x; 1.7692x over previous
#include <cuda_runtime.h>
#include <math.h>

#define NN   50000
#define EE   800000
#define IN_C 128
#define HID  256
#define EMBD 128
#define RR   4
#define NBLK ((NN + 255) / 256)   // 196 scan blocks

// ---------------- scratch (device globals; no allocation) ----------------
__device__ int      g_deg[NN];
__device__ float    g_invdeg[NN];
__device__ int      g_cnt4[NN * RR];
__device__ float    g_invcnt4[NN * RR];
__device__ int      g_rowstart[NN];
__device__ int      g_cursor[NN];
__device__ int      g_bsum[256];
__device__ int      g_boff[256];
__device__ int      g_es[EE];       // CSR: src per slot (sorted by dst)
__device__ int      g_etl[EE];      // CSR: edge type per slot
__device__ float    g_agg1[(size_t)NN * IN_C];
__device__ float    g_x1[(size_t)NN * HID];
__device__ float    g_agg2[(size_t)NN * HID];
__device__ float    g_xsage[(size_t)NN * HID];
__device__ float    g_h[(size_t)NN * 2 * HID];
__device__ float    g_als[NN * 2];
__device__ float    g_ald[NN * 2];
__device__ float    g_xgat[(size_t)NN * HID];
__device__ float    g_xt[(size_t)RR * NN * EMBD];
__device__ float    g_xrgcn[(size_t)NN * EMBD];

__device__ __forceinline__ float lrelu(float v) { return v > 0.f ? v : 0.2f * v; }

__device__ __forceinline__ unsigned f2tf32(float f) {
    unsigned r;
    asm("cvt.rna.tf32.f32 %0, %1;" : "=r"(r) : "f"(f));
    return r;
}

// ---------------- zero / counts ----------------
__global__ void k_zero_small() {
    int i = blockIdx.x * blockDim.x + threadIdx.x;
    if (i < NN) { g_deg[i] = 0; g_cursor[i] = 0; }
    if (i < NN * RR) g_cnt4[i] = 0;
}

__global__ void k_count(const int* __restrict__ dst, const int* __restrict__ et) {
    int i = blockIdx.x * blockDim.x + threadIdx.x;
    if (i >= EE) return;
    int d = dst[i];
    atomicAdd(&g_deg[d], 1);
    atomicAdd(&g_cnt4[d * RR + et[i]], 1);
}

__global__ void k_inv() {
    int i = blockIdx.x * blockDim.x + threadIdx.x;
    if (i >= NN) return;
    g_invdeg[i] = 1.f / fmaxf((float)g_deg[i], 1.f);
#pragma unroll
    for (int r = 0; r < RR; r++)
        g_invcnt4[i * RR + r] = 1.f / fmaxf((float)g_cnt4[i * RR + r], 1.f);
}

// ---------------- 3-kernel exclusive scan of g_deg -> g_rowstart ----------------
__global__ void k_scan1() {
    __shared__ int sh[256];
    int b = blockIdx.x, t = threadIdx.x;
    int i = b * 256 + t;
    int v = (i < NN) ? g_deg[i] : 0;
    sh[t] = v; __syncthreads();
    for (int o = 1; o < 256; o <<= 1) {
        int add = (t >= o) ? sh[t - o] : 0;
        __syncthreads();
        sh[t] += add;
        __syncthreads();
    }
    if (i < NN) g_rowstart[i] = sh[t] - v;
    if (t == 255) g_bsum[b] = sh[255];
}

__global__ void k_scan2() {
    __shared__ int sh[256];
    int t = threadIdx.x;
    int v = (t < NBLK) ? g_bsum[t] : 0;
    sh[t] = v; __syncthreads();
    for (int o = 1; o < 256; o <<= 1) {
        int add = (t >= o) ? sh[t - o] : 0;
        __syncthreads();
        sh[t] += add;
        __syncthreads();
    }
    g_boff[t] = sh[t] - v;
}

__global__ void k_scan3() {
    int i = blockIdx.x * blockDim.x + threadIdx.x;
    if (i < NN) g_rowstart[i] += g_boff[i >> 8];
}

__global__ void k_fill(const int* __restrict__ src, const int* __restrict__ dst,
                       const int* __restrict__ et) {
    int e = blockIdx.x * blockDim.x + threadIdx.x;
    if (e >= EE) return;
    int d = dst[e];
    int pos = atomicAdd(&g_cursor[d], 1);
    int slot = g_rowstart[d] + pos;
    g_es[slot] = src[e];
    g_etl[slot] = et[e];
}

// ---------------- SAGE mean-gather: one block per node, one thread per column ----------------
template <int D>
__global__ __launch_bounds__(D) void k_sage_gather(const float* __restrict__ xin,
                                                   float* __restrict__ agg) {
    int n = blockIdx.x;
    int c = threadIdx.x;
    int base = g_rowstart[n], deg = g_deg[n];
    const int* es = g_es + base;
    float acc = 0.f;
    int j = 0;
    for (; j + 4 <= deg; j += 4) {
        int s0 = es[j], s1 = es[j + 1], s2 = es[j + 2], s3 = es[j + 3];
        float v0 = xin[(size_t)s0 * D + c];
        float v1 = xin[(size_t)s1 * D + c];
        float v2 = xin[(size_t)s2 * D + c];
        float v3 = xin[(size_t)s3 * D + c];
        acc += (v0 + v1) + (v2 + v3);
    }
    for (; j < deg; j++) acc += xin[(size_t)es[j] * D + c];
    agg[(size_t)n * D + c] = acc * g_invdeg[n];
}

// ---------------- TF32 tensor-core GEMM: 128x128x16 tile, 8 warps, warp 32x64 ----------------
// As[m][k] row-major (pitch 20), Bs[n][k] n-major (pitch 20) — both feed ldmatrix.b16.x4
// which lands exactly on the m16n8k8.tf32 A/B fragment layouts.
__global__ __launch_bounds__(256) void tgemm(
    const float* __restrict__ A, const float* __restrict__ B, float* __restrict__ C,
    const float* __restrict__ bias,
    int M, int Nc, int K, int accFlag, int reluFlag) {
    __shared__ unsigned As[128][20];
    __shared__ unsigned Bs[128][20];
    const int tid = threadIdx.x;
    const int m0 = blockIdx.y * 128, n0 = blockIdx.x * 128;
    const int wid = tid >> 5, lane = tid & 31;
    const int wm = wid & 3, wn = wid >> 2;     // 4 warps x 32 rows, 2 warps x 64 cols
    const int g = lane >> 2, tq = lane & 3;

    float acc[2][8][4];
#pragma unroll
    for (int mt = 0; mt < 2; mt++)
#pragma unroll
        for (int nt = 0; nt < 8; nt++)
#pragma unroll
            for (int r = 0; r < 4; r++) acc[mt][nt][r] = 0.f;

    // A fill: thread -> row tid>>1 (128 rows), 8 cols starting (tid&1)*8
    const int aRow = tid >> 1;
    const int aCol = (tid & 1) * 8;
    const bool aValid = (m0 + aRow) < M;
    const float* Ag = A + (size_t)(aValid ? (m0 + aRow) : 0) * K + aCol;

    // ldmatrix per-lane row/col selectors
    const int aLr = (lane & 7) + (((lane >> 3) & 1) << 3);
    const int aLc = ((lane >> 4) & 1) * 4;
    const int bLr = (lane & 7) + (((lane >> 4) & 1) << 3);
    const int bLc = ((lane >> 3) & 1) * 4;

    for (int k0 = 0; k0 < K; k0 += 16) {
        // ---- fill A (2 x float4 per thread, cvt to tf32) ----
#pragma unroll
        for (int j = 0; j < 2; j++) {
            float4 v = make_float4(0.f, 0.f, 0.f, 0.f);
            if (aValid) v = *(const float4*)(Ag + k0 + j * 4);
            uint4 u;
            u.x = f2tf32(v.x); u.y = f2tf32(v.y); u.z = f2tf32(v.z); u.w = f2tf32(v.w);
            *(uint4*)&As[aRow][aCol + j * 4] = u;
        }
        // ---- fill B transposed: Bs[n][k] = B[k0+k][n0+n] (coalesced scalar reads) ----
#pragma unroll
        for (int p = 0; p < 8; p++) {
            int e = p * 256 + tid;
            int n = e & 127, k = e >> 7;
            Bs[n][k] = f2tf32(B[(size_t)(k0 + k) * Nc + n0 + n]);
        }
        __syncthreads();

#pragma unroll
        for (int ks = 0; ks < 16; ks += 8) {
            unsigned af[2][4], bf[4][4];
#pragma unroll
            for (int mt = 0; mt < 2; mt++) {
                unsigned addr = (unsigned)__cvta_generic_to_shared(
                    &As[wm * 32 + mt * 16 + aLr][ks + aLc]);
                asm volatile("ldmatrix.sync.aligned.m8n8.x4.shared.b16 {%0,%1,%2,%3}, [%4];"
                    : "=r"(af[mt][0]), "=r"(af[mt][1]), "=r"(af[mt][2]), "=r"(af[mt][3])
                    : "r"(addr));
            }
#pragma unroll
            for (int np = 0; np < 4; np++) {
                unsigned addr = (unsigned)__cvta_generic_to_shared(
                    &Bs[wn * 64 + np * 16 + bLr][ks + bLc]);
                asm volatile("ldmatrix.sync.aligned.m8n8.x4.shared.b16 {%0,%1,%2,%3}, [%4];"
                    : "=r"(bf[np][0]), "=r"(bf[np][1]), "=r"(bf[np][2]), "=r"(bf[np][3])
                    : "r"(addr));
            }
#pragma unroll
            for (int mt = 0; mt < 2; mt++)
#pragma unroll
                for (int nt = 0; nt < 8; nt++) {
                    unsigned b0 = bf[nt >> 1][(nt & 1) * 2 + 0];
                    unsigned b1 = bf[nt >> 1][(nt & 1) * 2 + 1];
                    float* c = acc[mt][nt];
                    asm volatile(
                        "mma.sync.aligned.m16n8k8.row.col.f32.tf32.tf32.f32 "
                        "{%0,%1,%2,%3}, {%4,%5,%6,%7}, {%8,%9}, {%0,%1,%2,%3};"
                        : "+f"(c[0]), "+f"(c[1]), "+f"(c[2]), "+f"(c[3])
                        : "r"(af[mt][0]), "r"(af[mt][1]), "r"(af[mt][2]), "r"(af[mt][3]),
                          "r"(b0), "r"(b1));
                }
        }
        __syncthreads();
    }

    // ---- epilogue ----
#pragma unroll
    for (int mt = 0; mt < 2; mt++) {
        int r0 = m0 + wm * 32 + mt * 16 + g;
#pragma unroll
        for (int half = 0; half < 2; half++) {
            int row = r0 + half * 8;
            if (row >= M) continue;
#pragma unroll
            for (int nt = 0; nt < 8; nt++) {
                int col = n0 + wn * 64 + nt * 8 + 2 * tq;
                float* p = C + (size_t)row * Nc + col;
                float2 cv;
                cv.x = acc[mt][nt][half * 2 + 0];
                cv.y = acc[mt][nt][half * 2 + 1];
                if (accFlag) { float2 o = *(const float2*)p; cv.x += o.x; cv.y += o.y; }
                if (bias != nullptr) { cv.x += bias[col]; cv.y += bias[col + 1]; }
                if (reluFlag) { cv.x = fmaxf(cv.x, 0.f); cv.y = fmaxf(cv.y, 0.f); }
                *(float2*)p = cv;
            }
        }
    }
}

// ---------------- GAT: per-node attention logits ----------------
__global__ __launch_bounds__(256) void k_al(const float* __restrict__ aS,
                                            const float* __restrict__ aD) {
    int gw = (int)(((size_t)blockIdx.x * blockDim.x + threadIdx.x) >> 5);
    int lane = threadIdx.x & 31;
    if (gw >= NN * 2) return;
    int n = gw >> 1, k = gw & 1;
    const float* hp = g_h + (size_t)n * 512 + k * 256;
    const float* as = aS + k * 256;
    const float* ad = aD + k * 256;
    float ss = 0.f, sd = 0.f;
    for (int d2 = lane; d2 < 256; d2 += 32) {
        float hv = hp[d2];
        ss += hv * as[d2];
        sd += hv * ad[d2];
    }
#pragma unroll
    for (int o = 16; o; o >>= 1) {
        ss += __shfl_down_sync(0xffffffffu, ss, o);
        sd += __shfl_down_sync(0xffffffffu, sd, o);
    }
    if (lane == 0) { g_als[gw] = ss; g_ald[gw] = sd; }
}

// ---------------- GAT: fused softmax + weighted gather, one block per node ----------------
__global__ __launch_bounds__(256) void k_gat(const float* __restrict__ bias) {
    __shared__ float sAl0[256], sAl1[256];
    __shared__ int   sS[256];
    __shared__ float red[256];
    int n = blockIdx.x;
    int t = threadIdx.x;
    int base = g_rowstart[n], deg = g_deg[n];

    float ald0 = g_ald[2 * n], ald1 = g_ald[2 * n + 1];
    float selfE0 = lrelu(g_als[2 * n] + ald0);
    float selfE1 = lrelu(g_als[2 * n + 1] + ald1);

    // pass A: per-head max over edges + self loop
    float m0 = selfE0, m1 = selfE1;
    for (int j = t; j < deg; j += 256) {
        int s = g_es[base + j];
        m0 = fmaxf(m0, lrelu(g_als[2 * s] + ald0));
        m1 = fmaxf(m1, lrelu(g_als[2 * s + 1] + ald1));
    }
    red[t] = m0; __syncthreads();
    for (int o = 128; o; o >>= 1) { if (t < o) red[t] = fmaxf(red[t], red[t + o]); __syncthreads(); }
    m0 = red[0]; __syncthreads();
    red[t] = m1; __syncthreads();
    for (int o = 128; o; o >>= 1) { if (t < o) red[t] = fmaxf(red[t], red[t + o]); __syncthreads(); }
    m1 = red[0]; __syncthreads();

    // pass B: denominator
    float d0 = (t == 0) ? expf(selfE0 - m0) : 0.f;
    float d1 = (t == 0) ? expf(selfE1 - m1) : 0.f;
    for (int j = t; j < deg; j += 256) {
        int s = g_es[base + j];
        d0 += expf(lrelu(g_als[2 * s] + ald0) - m0);
        d1 += expf(lrelu(g_als[2 * s + 1] + ald1) - m1);
    }
    red[t] = d0; __syncthreads();
    for (int o = 128; o; o >>= 1) { if (t < o) red[t] += red[t + o]; __syncthreads(); }
    d0 = red[0]; __syncthreads();
    red[t] = d1; __syncthreads();
    for (int o = 128; o; o >>= 1) { if (t < o) red[t] += red[t + o]; __syncthreads(); }
    d1 = red[0]; __syncthreads();
    float inv0 = 1.f / fmaxf(d0, 1e-16f);
    float inv1 = 1.f / fmaxf(d1, 1e-16f);

    // pass C: weighted gather (self loop + chunked edge list)
    const float* hn = g_h + (size_t)n * 512;
    float a0 = expf(selfE0 - m0) * inv0 * hn[t];
    float a1 = expf(selfE1 - m1) * inv1 * hn[256 + t];
    for (int c0 = 0; c0 < deg; c0 += 256) {
        int cnt = min(256, deg - c0);
        if (t < cnt) {
            int s = g_es[base + c0 + t];
            sS[t] = s;
            sAl0[t] = expf(lrelu(g_als[2 * s] + ald0) - m0) * inv0;
            sAl1[t] = expf(lrelu(g_als[2 * s + 1] + ald1) - m1) * inv1;
        }
        __syncthreads();
        for (int j = 0; j < cnt; j++) {
            const float* hs = g_h + (size_t)sS[j] * 512;
            a0 += sAl0[j] * hs[t];
            a1 += sAl1[j] * hs[256 + t];
        }
        __syncthreads();
    }
    float v = 0.5f * (a0 + a1) + bias[t];
    g_xgat[(size_t)n * 256 + t] = fmaxf(v, 0.f);
}

// ---------------- RGCN gather: per-relation mean folded into per-edge weight ----------------
__global__ __launch_bounds__(128) void k_rgcn() {
    int n = blockIdx.x;
    int c = threadIdx.x;
    int base = g_rowstart[n], deg = g_deg[n];
    float w0 = g_invcnt4[n * 4 + 0], w1 = g_invcnt4[n * 4 + 1];
    float w2 = g_invcnt4[n * 4 + 2], w3 = g_invcnt4[n * 4 + 3];
    float acc = 0.f;
#pragma unroll 2
    for (int j = 0; j < deg; j++) {
        int s = g_es[base + j];
        int r = g_etl[base + j];
        float w = (r == 0) ? w0 : (r == 1) ? w1 : (r == 2) ? w2 : w3;
        acc += w * g_xt[((size_t)r * NN + s) * EMBD + c];
    }
    g_xrgcn[(size_t)n * EMBD + c] = acc;
}

// ---------------- final L2 normalize ----------------
__global__ void k_norm(float* __restrict__ out) {
    int n = blockIdx.x;
    int t = threadIdx.x;   // 128 threads
    float v = out[(size_t)n * EMBD + t];
    float s = v * v;
#pragma unroll
    for (int o = 16; o; o >>= 1) s += __shfl_down_sync(0xffffffffu, s, o);
    __shared__ float sh[4];
    if ((t & 31) == 0) sh[t >> 5] = s;
    __syncthreads();
    float tot = sh[0] + sh[1] + sh[2] + sh[3];
    float nrm = fmaxf(sqrtf(tot), 1e-12f);
    out[(size_t)n * EMBD + t] = v / nrm;
}

// ---------------- host ----------------
static void launch_gemm(const float* A, const float* B, float* C, const float* bias,
                        int M, int Nc, int K, int acc, int relu) {
    dim3 grid(Nc / 128, (M + 127) / 128);
    tgemm<<<grid, 256>>>(A, B, C, bias, M, Nc, K, acc, relu);
}

extern "C" void kernel_launch(void* const* d_in, const int* in_sizes, int n_in,
                              void* d_out, int out_size) {
    const float* x    = (const float*)d_in[0];
    const int*   ei   = (const int*)d_in[1];
    const int*   et   = (const int*)d_in[2];
    const float* s1Wl = (const float*)d_in[3];
    const float* s1Wr = (const float*)d_in[4];
    const float* s1b  = (const float*)d_in[5];
    const float* s2Wl = (const float*)d_in[6];
    const float* s2Wr = (const float*)d_in[7];
    const float* s2b  = (const float*)d_in[8];
    const float* gatW = (const float*)d_in[9];
    const float* aSrc = (const float*)d_in[10];
    const float* aDst = (const float*)d_in[11];
    const float* gatB = (const float*)d_in[12];
    const float* Wrel = (const float*)d_in[13];
    const float* Wroot= (const float*)d_in[14];
    const float* rgcB = (const float*)d_in[15];
    const float* fW   = (const float*)d_in[16];
    const float* fB   = (const float*)d_in[17];
    float* out = (float*)d_out;

    const int* src = ei;
    const int* dst = ei + EE;

    float *p_agg1, *p_x1, *p_agg2, *p_xsage, *p_h, *p_xgat, *p_xt, *p_xrgcn;
    cudaGetSymbolAddress((void**)&p_agg1, g_agg1);
    cudaGetSymbolAddress((void**)&p_x1, g_x1);
    cudaGetSymbolAddress((void**)&p_agg2, g_agg2);
    cudaGetSymbolAddress((void**)&p_xsage, g_xsage);
    cudaGetSymbolAddress((void**)&p_h, g_h);
    cudaGetSymbolAddress((void**)&p_xgat, g_xgat);
    cudaGetSymbolAddress((void**)&p_xt, g_xt);
    cudaGetSymbolAddress((void**)&p_xrgcn, g_xrgcn);

    // ---- CSR build ----
    k_zero_small<<<(NN * RR + 255) / 256, 256>>>();
    k_count<<<(EE + 255) / 256, 256>>>(dst, et);
    k_inv<<<(NN + 255) / 256, 256>>>();
    k_scan1<<<NBLK, 256>>>();
    k_scan2<<<1, 256>>>();
    k_scan3<<<NBLK, 256>>>();
    k_fill<<<(EE + 255) / 256, 256>>>(src, dst, et);

    // ---- SAGE 1 ----
    k_sage_gather<IN_C><<<NN, IN_C>>>(x, p_agg1);
    launch_gemm(x, s1Wr, p_x1, nullptr, NN, HID, IN_C, 0, 0);
    launch_gemm(p_agg1, s1Wl, p_x1, s1b, NN, HID, IN_C, 1, 1);

    // ---- SAGE 2 ----
    k_sage_gather<HID><<<NN, HID>>>(p_x1, p_agg2);
    launch_gemm(p_x1, s2Wr, p_xsage, nullptr, NN, HID, HID, 0, 0);
    launch_gemm(p_agg2, s2Wl, p_xsage, s2b, NN, HID, HID, 1, 1);

    // ---- GAT ----
    launch_gemm(p_xsage, gatW, p_h, nullptr, NN, 2 * HID, HID, 0, 0);
    k_al<<<(NN * 2 * 32 + 255) / 256, 256>>>(aSrc, aDst);
    k_gat<<<NN, 256>>>(gatB);

    // ---- RGCN ----
    for (int r = 0; r < RR; r++)
        launch_gemm(p_xgat, Wrel + (size_t)r * HID * EMBD, p_xt + (size_t)r * NN * EMBD,
                    nullptr, NN, EMBD, HID, 0, 0);
    k_rgcn<<<NN, 128>>>();
    launch_gemm(p_xgat, Wroot, p_xrgcn, rgcB, NN, EMBD, HID, 1, 0);

    // ---- Fusion + normalize ----
    launch_gemm(p_xsage, fW,              out, nullptr, NN, EMBD, HID, 0, 0);
    launch_gemm(p_xgat,  fW + 256 * EMBD, out, nullptr, NN, EMBD, HID, 1, 0);
    launch_gemm(p_xrgcn, fW + 512 * EMBD, out, fB,      NN, EMBD, EMBD, 1, 0);
    k_norm<<<NN, 128>>>(out);
}

// round 5
// speedup vs baseline: 1.8916x; 1.0691x over previous
#include <cuda_runtime.h>
#include <math.h>

#define NN   50000
#define EE   800000
#define IN_C 128
#define HID  256
#define EMBD 128
#define RR   4
#define NBLK ((NN + 255) / 256)   // 196 scan blocks

// ---------------- scratch (device globals; no allocation) ----------------
__device__ int      g_deg[NN];
__device__ float    g_invdeg[NN];
__device__ int      g_cnt4[NN * RR];
__device__ float    g_invcnt4[NN * RR];
__device__ int      g_rowstart[NN];
__device__ int      g_cursor[NN];
__device__ int      g_bsum[256];
__device__ int      g_boff[256];
__device__ int      g_es[EE];       // CSR: src per slot (sorted by dst)
__device__ int      g_etl[EE];      // CSR: edge type per slot
__device__ float    g_agg1[(size_t)NN * IN_C];
__device__ float    g_x1[(size_t)NN * HID];
__device__ float    g_agg2[(size_t)NN * HID];
__device__ float    g_xsage[(size_t)NN * HID];
__device__ float    g_h[(size_t)NN * 2 * HID];
__device__ float    g_als[NN * 2];
__device__ float    g_ald[NN * 2];
__device__ float    g_xgat[(size_t)NN * HID];
__device__ float    g_xt[(size_t)RR * NN * EMBD];
__device__ float    g_xrgcn[(size_t)NN * EMBD];   // rgcn agg (no root)
__device__ float    g_fw2[HID * EMBD];            // F2 + Wroot@F3
__device__ float    g_fb2[EMBD];                  // fB + rgcB@F3

__device__ __forceinline__ float lrelu(float v) { return v > 0.f ? v : 0.2f * v; }

__device__ __forceinline__ unsigned f2tf32(float f) {
    unsigned r;
    asm("cvt.rna.tf32.f32 %0, %1;" : "=r"(r) : "f"(f));
    return r;
}

// ---------------- zero / counts ----------------
__global__ void k_zero_small() {
    int i = blockIdx.x * blockDim.x + threadIdx.x;
    if (i < NN) { g_deg[i] = 0; g_cursor[i] = 0; }
    if (i < NN * RR) g_cnt4[i] = 0;
}

__global__ void k_count(const int* __restrict__ dst, const int* __restrict__ et) {
    int i = blockIdx.x * blockDim.x + threadIdx.x;
    if (i >= EE) return;
    int d = dst[i];
    atomicAdd(&g_deg[d], 1);
    atomicAdd(&g_cnt4[d * RR + et[i]], 1);
}

// ---------------- scan of g_deg -> g_rowstart (3 kernels, inv fused in last) ----------------
__global__ void k_scan1() {
    __shared__ int sh[256];
    int b = blockIdx.x, t = threadIdx.x;
    int i = b * 256 + t;
    int v = (i < NN) ? g_deg[i] : 0;
    sh[t] = v; __syncthreads();
    for (int o = 1; o < 256; o <<= 1) {
        int add = (t >= o) ? sh[t - o] : 0;
        __syncthreads();
        sh[t] += add;
        __syncthreads();
    }
    if (i < NN) g_rowstart[i] = sh[t] - v;
    if (t == 255) g_bsum[b] = sh[255];
}

__global__ void k_scan2() {
    __shared__ int sh[256];
    int t = threadIdx.x;
    int v = (t < NBLK) ? g_bsum[t] : 0;
    sh[t] = v; __syncthreads();
    for (int o = 1; o < 256; o <<= 1) {
        int add = (t >= o) ? sh[t - o] : 0;
        __syncthreads();
        sh[t] += add;
        __syncthreads();
    }
    g_boff[t] = sh[t] - v;
}

__global__ void k_scan3_inv() {
    int i = blockIdx.x * blockDim.x + threadIdx.x;
    if (i >= NN) return;
    g_rowstart[i] += g_boff[i >> 8];
    g_invdeg[i] = 1.f / fmaxf((float)g_deg[i], 1.f);
#pragma unroll
    for (int r = 0; r < RR; r++)
        g_invcnt4[i * RR + r] = 1.f / fmaxf((float)g_cnt4[i * RR + r], 1.f);
}

__global__ void k_fill(const int* __restrict__ src, const int* __restrict__ dst,
                       const int* __restrict__ et) {
    int e = blockIdx.x * blockDim.x + threadIdx.x;
    if (e >= EE) return;
    int d = dst[e];
    int pos = atomicAdd(&g_cursor[d], 1);
    int slot = g_rowstart[d] + pos;
    g_es[slot] = src[e];
    g_etl[slot] = et[e];
}

// ---------------- SAGE mean-gather ----------------
template <int D>
__global__ __launch_bounds__(D) void k_sage_gather(const float* __restrict__ xin,
                                                   float* __restrict__ agg) {
    int n = blockIdx.x;
    int c = threadIdx.x;
    int base = g_rowstart[n], deg = g_deg[n];
    const int* es = g_es + base;
    float acc = 0.f;
    int j = 0;
    for (; j + 4 <= deg; j += 4) {
        int s0 = es[j], s1 = es[j + 1], s2 = es[j + 2], s3 = es[j + 3];
        float v0 = xin[(size_t)s0 * D + c];
        float v1 = xin[(size_t)s1 * D + c];
        float v2 = xin[(size_t)s2 * D + c];
        float v3 = xin[(size_t)s3 * D + c];
        acc += (v0 + v1) + (v2 + v3);
    }
    for (; j < deg; j++) acc += xin[(size_t)es[j] * D + c];
    agg[(size_t)n * D + c] = acc * g_invdeg[n];
}

// ---------------- TF32 tensor-core GEMM, multi-segment A/B, double-buffered ----------------
// C[M,Nc] = sum_s A_s[M,K_s] @ B_s[K_s,Nc]  (+C if acc) (+bias) (relu)
// grid.z batching: B_s0 += z*zsB, C += z*zsC.
__global__ __launch_bounds__(256) void tgemm(
    const float* __restrict__ A0, const float* __restrict__ B0, int K0,
    const float* __restrict__ A1, const float* __restrict__ B1, int K1,
    const float* __restrict__ A2, const float* __restrict__ B2, int K2,
    float* __restrict__ C, const float* __restrict__ bias,
    int M, int Nc, int accFlag, int reluFlag,
    size_t zsB, size_t zsC) {
    __shared__ unsigned As[2][128][20];
    __shared__ unsigned Bs[2][128][20];
    const int tid = threadIdx.x;
    const int m0 = blockIdx.y * 128, n0 = blockIdx.x * 128;
    const int wid = tid >> 5, lane = tid & 31;
    const int wm = wid & 3, wn = wid >> 2;
    const int g = lane >> 2, tq = lane & 3;

    const float* segA[3] = {A0, A1, A2};
    const float* segB[3] = {B0 + blockIdx.z * zsB, B1, B2};
    int segK[3] = {K0, K1, K2};
    C += blockIdx.z * zsC;
    const int T = (K0 + K1 + K2) >> 4;

    float acc[2][8][4];
#pragma unroll
    for (int mt = 0; mt < 2; mt++)
#pragma unroll
        for (int nt = 0; nt < 8; nt++)
#pragma unroll
            for (int r = 0; r < 4; r++) acc[mt][nt][r] = 0.f;

    const int aRow = tid >> 1;
    const int aCol = (tid & 1) * 8;
    const bool aValid = (m0 + aRow) < M;
    const int bN = tid & 127;          // B fill: this thread's n
    const int bK0 = tid >> 7;          // and base k (0/1), stepping by 2

    const int aLr = (lane & 7) + (((lane >> 3) & 1) << 3);
    const int aLc = ((lane >> 4) & 1) * 4;
    const int bLr = (lane & 7) + (((lane >> 4) & 1) << 3);
    const int bLc = ((lane >> 3) & 1) * 4;

    float apre[8], bpre[8];
    int s = 0, k0 = 0;

    // prologue: load tile 0 -> regs -> smem buf0
    {
        const float* Ag = segA[s] + (size_t)(aValid ? (m0 + aRow) : 0) * segK[s] + k0 + aCol;
#pragma unroll
        for (int j = 0; j < 2; j++) {
            float4 v = make_float4(0.f, 0.f, 0.f, 0.f);
            if (aValid) v = *(const float4*)(Ag + j * 4);
            apre[j * 4 + 0] = v.x; apre[j * 4 + 1] = v.y;
            apre[j * 4 + 2] = v.z; apre[j * 4 + 3] = v.w;
        }
        const float* Bg = segB[s] + (size_t)k0 * Nc + n0 + bN;
#pragma unroll
        for (int p = 0; p < 8; p++)
            bpre[p] = Bg[(size_t)(bK0 + 2 * p) * Nc];
#pragma unroll
        for (int j = 0; j < 8; j++) As[0][aRow][aCol + j] = f2tf32(apre[j]);
#pragma unroll
        for (int p = 0; p < 8; p++) Bs[0][bN][bK0 + 2 * p] = f2tf32(bpre[p]);
    }
    __syncthreads();

    for (int t = 0; t < T; t++) {
        const int pb = t & 1;
        bool have_next = (t + 1 < T);
        int s_n = s, k_n = k0;
        if (have_next) {
            k_n += 16;
            if (k_n >= segK[s_n]) {
                s_n++; k_n = 0;
                while (segK[s_n] == 0) s_n++;
            }
            const float* Ag = segA[s_n] + (size_t)(aValid ? (m0 + aRow) : 0) * segK[s_n] + k_n + aCol;
#pragma unroll
            for (int j = 0; j < 2; j++) {
                float4 v = make_float4(0.f, 0.f, 0.f, 0.f);
                if (aValid) v = *(const float4*)(Ag + j * 4);
                apre[j * 4 + 0] = v.x; apre[j * 4 + 1] = v.y;
                apre[j * 4 + 2] = v.z; apre[j * 4 + 3] = v.w;
            }
            const float* Bg = segB[s_n] + (size_t)k_n * Nc + n0 + bN;
#pragma unroll
            for (int p = 0; p < 8; p++)
                bpre[p] = Bg[(size_t)(bK0 + 2 * p) * Nc];
        }

        // compute current tile from buf pb
#pragma unroll
        for (int ks = 0; ks < 16; ks += 8) {
            unsigned af[2][4], bf[4][4];
#pragma unroll
            for (int mt = 0; mt < 2; mt++) {
                unsigned addr = (unsigned)__cvta_generic_to_shared(
                    &As[pb][wm * 32 + mt * 16 + aLr][ks + aLc]);
                asm volatile("ldmatrix.sync.aligned.m8n8.x4.shared.b16 {%0,%1,%2,%3}, [%4];"
                    : "=r"(af[mt][0]), "=r"(af[mt][1]), "=r"(af[mt][2]), "=r"(af[mt][3])
                    : "r"(addr));
            }
#pragma unroll
            for (int np = 0; np < 4; np++) {
                unsigned addr = (unsigned)__cvta_generic_to_shared(
                    &Bs[pb][wn * 64 + np * 16 + bLr][ks + bLc]);
                asm volatile("ldmatrix.sync.aligned.m8n8.x4.shared.b16 {%0,%1,%2,%3}, [%4];"
                    : "=r"(bf[np][0]), "=r"(bf[np][1]), "=r"(bf[np][2]), "=r"(bf[np][3])
                    : "r"(addr));
            }
#pragma unroll
            for (int mt = 0; mt < 2; mt++)
#pragma unroll
                for (int nt = 0; nt < 8; nt++) {
                    unsigned b0 = bf[nt >> 1][(nt & 1) * 2 + 0];
                    unsigned b1 = bf[nt >> 1][(nt & 1) * 2 + 1];
                    float* c = acc[mt][nt];
                    asm volatile(
                        "mma.sync.aligned.m16n8k8.row.col.f32.tf32.tf32.f32 "
                        "{%0,%1,%2,%3}, {%4,%5,%6,%7}, {%8,%9}, {%0,%1,%2,%3};"
                        : "+f"(c[0]), "+f"(c[1]), "+f"(c[2]), "+f"(c[3])
                        : "r"(af[mt][0]), "r"(af[mt][1]), "r"(af[mt][2]), "r"(af[mt][3]),
                          "r"(b0), "r"(b1));
                }
        }

        if (have_next) {
            const int nb = pb ^ 1;
#pragma unroll
            for (int j = 0; j < 8; j++) As[nb][aRow][aCol + j] = f2tf32(apre[j]);
#pragma unroll
            for (int p = 0; p < 8; p++) Bs[nb][bN][bK0 + 2 * p] = f2tf32(bpre[p]);
        }
        __syncthreads();
        s = s_n; k0 = k_n;
    }

    // ---- epilogue ----
#pragma unroll
    for (int mt = 0; mt < 2; mt++) {
        int r0 = m0 + wm * 32 + mt * 16 + g;
#pragma unroll
        for (int half = 0; half < 2; half++) {
            int row = r0 + half * 8;
            if (row >= M) continue;
#pragma unroll
            for (int nt = 0; nt < 8; nt++) {
                int col = n0 + wn * 64 + nt * 8 + 2 * tq;
                float* p = C + (size_t)row * Nc + col;
                float2 cv;
                cv.x = acc[mt][nt][half * 2 + 0];
                cv.y = acc[mt][nt][half * 2 + 1];
                if (accFlag) { float2 o = *(const float2*)p; cv.x += o.x; cv.y += o.y; }
                if (bias != nullptr) { cv.x += bias[col]; cv.y += bias[col + 1]; }
                if (reluFlag) { cv.x = fmaxf(cv.x, 0.f); cv.y = fmaxf(cv.y, 0.f); }
                *(float2*)p = cv;
            }
        }
    }
}

// ---------------- GAT: per-node attention logits ----------------
__global__ __launch_bounds__(256) void k_al(const float* __restrict__ aS,
                                            const float* __restrict__ aD) {
    int gw = (int)(((size_t)blockIdx.x * blockDim.x + threadIdx.x) >> 5);
    int lane = threadIdx.x & 31;
    if (gw >= NN * 2) return;
    int n = gw >> 1, k = gw & 1;
    const float* hp = g_h + (size_t)n * 512 + k * 256;
    const float* as = aS + k * 256;
    const float* ad = aD + k * 256;
    float ss = 0.f, sd = 0.f;
    for (int d2 = lane; d2 < 256; d2 += 32) {
        float hv = hp[d2];
        ss += hv * as[d2];
        sd += hv * ad[d2];
    }
#pragma unroll
    for (int o = 16; o; o >>= 1) {
        ss += __shfl_down_sync(0xffffffffu, ss, o);
        sd += __shfl_down_sync(0xffffffffu, sd, o);
    }
    if (lane == 0) { g_als[gw] = ss; g_ald[gw] = sd; }
}

// ---------------- GAT: single-pass online-softmax weighted gather ----------------
__global__ __launch_bounds__(256) void k_gat(const float* __restrict__ bias) {
    __shared__ float sW0[256], sW1[256];
    __shared__ int   sS[256];
    __shared__ float red[256];
    int n = blockIdx.x;
    int t = threadIdx.x;
    int base = g_rowstart[n], deg = g_deg[n];

    float ald0 = g_ald[2 * n], ald1 = g_ald[2 * n + 1];
    float m0 = lrelu(g_als[2 * n] + ald0);       // self-loop logit = initial max
    float m1 = lrelu(g_als[2 * n + 1] + ald1);
    float d0 = 1.f, d1 = 1.f;                    // exp(self - m) = 1
    const float* hn = g_h + (size_t)n * 512;
    float a0 = hn[t];
    float a1 = hn[256 + t];

    for (int c0 = 0; c0 < deg; c0 += 256) {
        int cnt = min(256, deg - c0);
        float e0 = -1e30f, e1 = -1e30f;
        int sNode = 0;
        if (t < cnt) {
            sNode = g_es[base + c0 + t];
            e0 = lrelu(g_als[2 * sNode] + ald0);
            e1 = lrelu(g_als[2 * sNode + 1] + ald1);
        }
        // chunk max (both heads)
        red[t] = e0; __syncthreads();
        for (int o = 128; o; o >>= 1) { if (t < o) red[t] = fmaxf(red[t], red[t + o]); __syncthreads(); }
        float cm0 = red[0]; __syncthreads();
        red[t] = e1; __syncthreads();
        for (int o = 128; o; o >>= 1) { if (t < o) red[t] = fmaxf(red[t], red[t + o]); __syncthreads(); }
        float cm1 = red[0]; __syncthreads();

        float M0 = fmaxf(m0, cm0), M1 = fmaxf(m1, cm1);
        float sc0 = expf(m0 - M0), sc1 = expf(m1 - M1);
        a0 *= sc0; d0 *= sc0; m0 = M0;
        a1 *= sc1; d1 *= sc1; m1 = M1;

        if (t < cnt) {
            sS[t] = sNode;
            sW0[t] = expf(e0 - m0);
            sW1[t] = expf(e1 - m1);
        }
        __syncthreads();
        for (int j = 0; j < cnt; j++) {
            float w0 = sW0[j], w1 = sW1[j];
            const float* hs = g_h + (size_t)sS[j] * 512;
            a0 += w0 * hs[t];
            a1 += w1 * hs[256 + t];
            d0 += w0; d1 += w1;
        }
        __syncthreads();
    }
    float v = 0.5f * (a0 / fmaxf(d0, 1e-16f) + a1 / fmaxf(d1, 1e-16f)) + bias[t];
    g_xgat[(size_t)n * 256 + t] = fmaxf(v, 0.f);
}

// ---------------- RGCN gather (agg only; root folded into fusion) ----------------
__global__ __launch_bounds__(128) void k_rgcn() {
    int n = blockIdx.x;
    int c = threadIdx.x;
    int base = g_rowstart[n], deg = g_deg[n];
    float w0 = g_invcnt4[n * 4 + 0], w1 = g_invcnt4[n * 4 + 1];
    float w2 = g_invcnt4[n * 4 + 2], w3 = g_invcnt4[n * 4 + 3];
    float acc = 0.f;
#pragma unroll 2
    for (int j = 0; j < deg; j++) {
        int s = g_es[base + j];
        int r = g_etl[base + j];
        float w = (r == 0) ? w0 : (r == 1) ? w1 : (r == 2) ? w2 : w3;
        acc += w * g_xt[((size_t)r * NN + s) * EMBD + c];
    }
    g_xrgcn[(size_t)n * EMBD + c] = acc;
}

// ---------------- fold rgcn root into fusion weights (fp32) ----------------
// g_fw2 = F2 + Wroot@F3 ;  g_fb2 = fB + rgcB@F3   (F2 = fW rows 256..511, F3 = rows 512..639)
__global__ void k_compose(const float* __restrict__ fW, const float* __restrict__ fB,
                          const float* __restrict__ Wroot, const float* __restrict__ rgcB) {
    int b = blockIdx.x, t = threadIdx.x;   // 128 threads
    const float* F3 = fW + 512 * EMBD;
    if (b < HID) {
        float acc = fW[(256 + b) * EMBD + t];
        for (int h = 0; h < EMBD; h++)
            acc += Wroot[b * EMBD + h] * F3[h * EMBD + t];
        g_fw2[b * EMBD + t] = acc;
    } else {
        float acc = fB[t];
        for (int h = 0; h < EMBD; h++)
            acc += rgcB[h] * F3[h * EMBD + t];
        g_fb2[t] = acc;
    }
}

// ---------------- final L2 normalize ----------------
__global__ void k_norm(float* __restrict__ out) {
    int n = blockIdx.x;
    int t = threadIdx.x;   // 128 threads
    float v = out[(size_t)n * EMBD + t];
    float s = v * v;
#pragma unroll
    for (int o = 16; o; o >>= 1) s += __shfl_down_sync(0xffffffffu, s, o);
    __shared__ float sh[4];
    if ((t & 31) == 0) sh[t >> 5] = s;
    __syncthreads();
    float tot = sh[0] + sh[1] + sh[2] + sh[3];
    float nrm = fmaxf(sqrtf(tot), 1e-12f);
    out[(size_t)n * EMBD + t] = v / nrm;
}

// ---------------- host ----------------
static void launch_seg(const float* A0, const float* B0, int K0,
                       const float* A1, const float* B1, int K1,
                       const float* A2, const float* B2, int K2,
                       float* C, const float* bias, int M, int Nc,
                       int acc, int relu, int gz = 1, size_t zsB = 0, size_t zsC = 0) {
    dim3 grid(Nc / 128, (M + 127) / 128, gz);
    tgemm<<<grid, 256>>>(A0, B0, K0, A1, B1, K1, A2, B2, K2,
                         C, bias, M, Nc, acc, relu, zsB, zsC);
}

extern "C" void kernel_launch(void* const* d_in, const int* in_sizes, int n_in,
                              void* d_out, int out_size) {
    const float* x    = (const float*)d_in[0];
    const int*   ei   = (const int*)d_in[1];
    const int*   et   = (const int*)d_in[2];
    const float* s1Wl = (const float*)d_in[3];
    const float* s1Wr = (const float*)d_in[4];
    const float* s1b  = (const float*)d_in[5];
    const float* s2Wl = (const float*)d_in[6];
    const float* s2Wr = (const float*)d_in[7];
    const float* s2b  = (const float*)d_in[8];
    const float* gatW = (const float*)d_in[9];
    const float* aSrc = (const float*)d_in[10];
    const float* aDst = (const float*)d_in[11];
    const float* gatB = (const float*)d_in[12];
    const float* Wrel = (const float*)d_in[13];
    const float* Wroot= (const float*)d_in[14];
    const float* rgcB = (const float*)d_in[15];
    const float* fW   = (const float*)d_in[16];
    const float* fB   = (const float*)d_in[17];
    float* out = (float*)d_out;

    const int* src = ei;
    const int* dst = ei + EE;

    float *p_agg1, *p_x1, *p_agg2, *p_xsage, *p_h, *p_xgat, *p_xt, *p_xrgcn, *p_fw2, *p_fb2;
    cudaGetSymbolAddress((void**)&p_agg1, g_agg1);
    cudaGetSymbolAddress((void**)&p_x1, g_x1);
    cudaGetSymbolAddress((void**)&p_agg2, g_agg2);
    cudaGetSymbolAddress((void**)&p_xsage, g_xsage);
    cudaGetSymbolAddress((void**)&p_h, g_h);
    cudaGetSymbolAddress((void**)&p_xgat, g_xgat);
    cudaGetSymbolAddress((void**)&p_xt, g_xt);
    cudaGetSymbolAddress((void**)&p_xrgcn, g_xrgcn);
    cudaGetSymbolAddress((void**)&p_fw2, g_fw2);
    cudaGetSymbolAddress((void**)&p_fb2, g_fb2);

    // ---- CSR build (GEMM at 4th launch so ncu -s5 profiles it) ----
    k_zero_small<<<(NN * RR + 255) / 256, 256>>>();                         // 1
    k_count<<<(EE + 255) / 256, 256>>>(dst, et);                            // 2
    k_scan1<<<NBLK, 256>>>();                                               // 3
    launch_seg(x, s1Wr, IN_C, 0, 0, 0, 0, 0, 0, p_x1, nullptr,
               NN, HID, 0, 0);                                              // 4: x@Wr -> x1
    k_scan2<<<1, 256>>>();                                                  // 5
    k_scan3_inv<<<NBLK, 256>>>();                                           // 6
    k_fill<<<(EE + 255) / 256, 256>>>(src, dst, et);                        // 7

    // ---- SAGE 1 (second half) ----
    k_sage_gather<IN_C><<<NN, IN_C>>>(x, p_agg1);
    launch_seg(p_agg1, s1Wl, IN_C, 0, 0, 0, 0, 0, 0, p_x1, s1b,
               NN, HID, 1, 1);

    // ---- SAGE 2 (single fused dual-A GEMM) ----
    k_sage_gather<HID><<<NN, HID>>>(p_x1, p_agg2);
    launch_seg(p_agg2, s2Wl, HID, p_x1, s2Wr, HID, 0, 0, 0, p_xsage, s2b,
               NN, HID, 0, 1);

    // ---- GAT ----
    launch_seg(p_xsage, gatW, HID, 0, 0, 0, 0, 0, 0, p_h, nullptr,
               NN, 2 * HID, 0, 0);
    k_al<<<(NN * 2 * 32 + 255) / 256, 256>>>(aSrc, aDst);
    k_gat<<<NN, 256>>>(gatB);

    // ---- RGCN (4 relations batched via grid.z) ----
    launch_seg(p_xgat, Wrel, HID, 0, 0, 0, 0, 0, 0, p_xt, nullptr,
               NN, EMBD, 0, 0, RR, (size_t)HID * EMBD, (size_t)NN * EMBD);
    k_rgcn<<<NN, 128>>>();
    k_compose<<<HID + 1, EMBD>>>(fW, fB, Wroot, rgcB);

    // ---- Fusion (3-segment GEMM, rgcn-root folded) + normalize ----
    launch_seg(p_xsage, fW, HID, p_xgat, p_fw2, HID, p_xrgcn, fW + 512 * EMBD, EMBD,
               out, p_fb2, NN, EMBD, 0, 0);
    k_norm<<<NN, 128>>>(out);
}

// round 6
// speedup vs baseline: 2.0327x; 1.0746x over previous
#include <cuda_runtime.h>
#include <math.h>

#define NN   50000
#define EE   800000
#define IN_C 128
#define HID  256
#define EMBD 128
#define RR   4
#define NBLK ((NN + 255) / 256)   // 196 scan blocks

// ---------------- scratch (device globals; no allocation) ----------------
__device__ int      g_deg[NN];
__device__ float    g_invdeg[NN];
__device__ int      g_cnt4[NN * RR];
__device__ float    g_invcnt4[NN * RR];
__device__ int      g_rowstart[NN];
__device__ int      g_cursor[NN];
__device__ int      g_bsum[256];
__device__ int      g_boff[256];
__device__ int      g_es[EE];
__device__ int      g_etl[EE];
__device__ float    g_xr[(size_t)NN * IN_C];       // tf32-rounded copy of x
__device__ float    g_agg1[(size_t)NN * IN_C];
__device__ float    g_x1[(size_t)NN * HID];
__device__ float    g_agg2[(size_t)NN * HID];
__device__ float    g_xsage[(size_t)NN * HID];
__device__ float    g_h[(size_t)NN * 2 * HID];
__device__ float    g_als[NN * 2];
__device__ float    g_ald[NN * 2];
__device__ float    g_xgat[(size_t)NN * HID];
__device__ float    g_xt[(size_t)RR * NN * EMBD];
__device__ float    g_xrgcn[(size_t)NN * EMBD];
__device__ float    g_fb2[EMBD];
// pre-transposed + tf32-rounded weights: Bt[n][k] row-major
__device__ float    g_bt1r[256 * 128];
__device__ float    g_bt1l[256 * 128];
__device__ float    g_bt2[256 * 512];
__device__ float    g_btg[512 * 256];
__device__ float    g_btrel[RR * 128 * 256];
__device__ float    g_btfus[128 * 640];

__device__ __forceinline__ float lrelu(float v) { return v > 0.f ? v : 0.2f * v; }

__device__ __forceinline__ unsigned f2tf32(float f) {
    unsigned r;
    asm("cvt.rna.tf32.f32 %0, %1;" : "=r"(r) : "f"(f));
    return r;
}
__device__ __forceinline__ float rtf(float f) { return __uint_as_float(f2tf32(f)); }

#define CP16(sm, gm) asm volatile("cp.async.cg.shared.global [%0], [%1], 16;" :: "r"(sm), "l"(gm))
#define CPCOMMIT()   asm volatile("cp.async.commit_group;")
#define CPWAIT(n)    asm volatile("cp.async.wait_group %0;" :: "n"(n))

// ---------------- zero / counts ----------------
__global__ void k_zero_small() {
    int i = blockIdx.x * blockDim.x + threadIdx.x;
    if (i < NN) { g_deg[i] = 0; g_cursor[i] = 0; }
    if (i < NN * RR) g_cnt4[i] = 0;
}

__global__ void k_count(const int* __restrict__ dst, const int* __restrict__ et) {
    int i = blockIdx.x * blockDim.x + threadIdx.x;
    if (i >= EE) return;
    int d = dst[i];
    atomicAdd(&g_deg[d], 1);
    atomicAdd(&g_cnt4[d * RR + et[i]], 1);
}

__global__ void k_scan1() {
    __shared__ int sh[256];
    int b = blockIdx.x, t = threadIdx.x;
    int i = b * 256 + t;
    int v = (i < NN) ? g_deg[i] : 0;
    sh[t] = v; __syncthreads();
    for (int o = 1; o < 256; o <<= 1) {
        int add = (t >= o) ? sh[t - o] : 0;
        __syncthreads();
        sh[t] += add;
        __syncthreads();
    }
    if (i < NN) g_rowstart[i] = sh[t] - v;
    if (t == 255) g_bsum[b] = sh[255];
}

__global__ void k_scan2() {
    __shared__ int sh[256];
    int t = threadIdx.x;
    int v = (t < NBLK) ? g_bsum[t] : 0;
    sh[t] = v; __syncthreads();
    for (int o = 1; o < 256; o <<= 1) {
        int add = (t >= o) ? sh[t - o] : 0;
        __syncthreads();
        sh[t] += add;
        __syncthreads();
    }
    g_boff[t] = sh[t] - v;
}

__global__ void k_scan3_inv() {
    int i = blockIdx.x * blockDim.x + threadIdx.x;
    if (i >= NN) return;
    g_rowstart[i] += g_boff[i >> 8];
    g_invdeg[i] = 1.f / fmaxf((float)g_deg[i], 1.f);
#pragma unroll
    for (int r = 0; r < RR; r++)
        g_invcnt4[i * RR + r] = 1.f / fmaxf((float)g_cnt4[i * RR + r], 1.f);
}

__global__ void k_fill(const int* __restrict__ src, const int* __restrict__ dst,
                       const int* __restrict__ et) {
    int e = blockIdx.x * blockDim.x + threadIdx.x;
    if (e >= EE) return;
    int d = dst[e];
    int pos = atomicAdd(&g_cursor[d], 1);
    int slot = g_rowstart[d] + pos;
    g_es[slot] = src[e];
    g_etl[slot] = et[e];
}

// ---------------- weight transpose (+tf32 round): Bt[n][kOff+k] = B[k][n] ----------------
__global__ void k_transB(const float* __restrict__ B, float* __restrict__ Bt,
                         int K, int N, int ldBt, int kOff) {
    int i = blockIdx.x * blockDim.x + threadIdx.x;
    if (i >= K * N) return;
    int k = i / N, n = i % N;
    Bt[(size_t)n * ldBt + kOff + k] = rtf(B[(size_t)k * N + n]);
}

// ---------------- tf32 round-copy ----------------
__global__ void k_round4(const float4* __restrict__ in, float4* __restrict__ out, int n4) {
    int i = blockIdx.x * blockDim.x + threadIdx.x;
    if (i >= n4) return;
    float4 v = in[i];
    v.x = rtf(v.x); v.y = rtf(v.y); v.z = rtf(v.z); v.w = rtf(v.w);
    out[i] = v;
}

// ---------------- SAGE mean-gather (stores tf32-rounded) ----------------
template <int D>
__global__ __launch_bounds__(D) void k_sage_gather(const float* __restrict__ xin,
                                                   float* __restrict__ agg) {
    int n = blockIdx.x;
    int c = threadIdx.x;
    int base = g_rowstart[n], deg = g_deg[n];
    const int* es = g_es + base;
    float acc = 0.f;
    int j = 0;
    for (; j + 4 <= deg; j += 4) {
        int s0 = es[j], s1 = es[j + 1], s2 = es[j + 2], s3 = es[j + 3];
        float v0 = xin[(size_t)s0 * D + c];
        float v1 = xin[(size_t)s1 * D + c];
        float v2 = xin[(size_t)s2 * D + c];
        float v3 = xin[(size_t)s3 * D + c];
        acc += (v0 + v1) + (v2 + v3);
    }
    for (; j < deg; j++) acc += xin[(size_t)es[j] * D + c];
    agg[(size_t)n * D + c] = rtf(acc * g_invdeg[n]);
}

// ---------------- TF32 GEMM: cp.async double-buffered, multi-segment A, pre-transposed B ----
// C = sum_s A_s[M,K_s] @ Bt^T  (Bt is [Nc][Ktot] row-major, pre-rounded)
__global__ __launch_bounds__(256) void tgemm(
    const float* __restrict__ A0, int K0,
    const float* __restrict__ A1, int K1,
    const float* __restrict__ A2, int K2,
    const float* __restrict__ Bt,
    float* __restrict__ C, const float* __restrict__ bias,
    int M, int Nc, int accFlag, int reluFlag, int roundFlag,
    size_t zsB, size_t zsC) {
    __shared__ __align__(16) float As[2][128][20];
    __shared__ __align__(16) float Bs[2][128][20];
    const int tid = threadIdx.x;
    const int m0 = blockIdx.y * 128, n0 = blockIdx.x * 128;
    const int wid = tid >> 5, lane = tid & 31;
    const int wm = wid & 3, wn = wid >> 2;
    const int g = lane >> 2, tq = lane & 3;
    const int Ktot = K0 + K1 + K2;
    Bt += blockIdx.z * zsB;
    C  += blockIdx.z * zsC;
    const float* segA[3] = {A0, A1, A2};
    const int segK[3] = {K0, K1, K2};
    const int segS[3] = {0, K0, K0 + K1};
    const int T = Ktot >> 4;

    float acc[2][8][4];
#pragma unroll
    for (int mt = 0; mt < 2; mt++)
#pragma unroll
        for (int nt = 0; nt < 8; nt++)
#pragma unroll
            for (int r = 0; r < 4; r++) acc[mt][nt][r] = 0.f;

    const int aRow = tid >> 1;
    const int aCol = (tid & 1) * 8;
    const bool aValid = (m0 + aRow) < M;
    const int aR = aValid ? (m0 + aRow) : 0;
    const float* BtRow = Bt + (size_t)(n0 + aRow) * Ktot + aCol;   // same thread shape for B

    const int aLr = (lane & 7) + (((lane >> 3) & 1) << 3);
    const int aLc = ((lane >> 4) & 1) * 4;
    const int bLr = (lane & 7) + (((lane >> 4) & 1) << 3);
    const int bLc = ((lane >> 3) & 1) * 4;

    int s = 0, k0v = 0;

    // prologue: issue tile 0
    {
        const float* Ag = segA[0] + (size_t)aR * segK[0] + aCol;
        unsigned sa = (unsigned)__cvta_generic_to_shared(&As[0][aRow][aCol]);
        CP16(sa, Ag); CP16(sa + 16, Ag + 4);
        unsigned sb = (unsigned)__cvta_generic_to_shared(&Bs[0][aRow][aCol]);
        CP16(sb, BtRow); CP16(sb + 16, BtRow + 4);
        CPCOMMIT();
    }

    for (int t = 0; t < T; t++) {
        const int pb = t & 1;
        bool hn = (t + 1 < T);
        int s_n = s, k_n = k0v;
        if (hn) {
            k_n += 16;
            if (k_n >= segK[s_n]) { s_n++; k_n = 0; while (segK[s_n] == 0) s_n++; }
            const float* Ag = segA[s_n] + (size_t)aR * segK[s_n] + k_n + aCol;
            unsigned sa = (unsigned)__cvta_generic_to_shared(&As[pb ^ 1][aRow][aCol]);
            CP16(sa, Ag); CP16(sa + 16, Ag + 4);
            const float* Bg = BtRow + segS[s_n] + k_n;
            unsigned sb = (unsigned)__cvta_generic_to_shared(&Bs[pb ^ 1][aRow][aCol]);
            CP16(sb, Bg); CP16(sb + 16, Bg + 4);
            CPCOMMIT();
            CPWAIT(1);
        } else {
            CPWAIT(0);
        }
        __syncthreads();

#pragma unroll
        for (int ks = 0; ks < 16; ks += 8) {
            unsigned af[2][4], bf[4][4];
#pragma unroll
            for (int mt = 0; mt < 2; mt++) {
                unsigned addr = (unsigned)__cvta_generic_to_shared(
                    &As[pb][wm * 32 + mt * 16 + aLr][ks + aLc]);
                asm volatile("ldmatrix.sync.aligned.m8n8.x4.shared.b16 {%0,%1,%2,%3}, [%4];"
                    : "=r"(af[mt][0]), "=r"(af[mt][1]), "=r"(af[mt][2]), "=r"(af[mt][3])
                    : "r"(addr));
            }
#pragma unroll
            for (int np = 0; np < 4; np++) {
                unsigned addr = (unsigned)__cvta_generic_to_shared(
                    &Bs[pb][wn * 64 + np * 16 + bLr][ks + bLc]);
                asm volatile("ldmatrix.sync.aligned.m8n8.x4.shared.b16 {%0,%1,%2,%3}, [%4];"
                    : "=r"(bf[np][0]), "=r"(bf[np][1]), "=r"(bf[np][2]), "=r"(bf[np][3])
                    : "r"(addr));
            }
#pragma unroll
            for (int mt = 0; mt < 2; mt++)
#pragma unroll
                for (int nt = 0; nt < 8; nt++) {
                    unsigned b0 = bf[nt >> 1][(nt & 1) * 2 + 0];
                    unsigned b1 = bf[nt >> 1][(nt & 1) * 2 + 1];
                    float* c = acc[mt][nt];
                    asm volatile(
                        "mma.sync.aligned.m16n8k8.row.col.f32.tf32.tf32.f32 "
                        "{%0,%1,%2,%3}, {%4,%5,%6,%7}, {%8,%9}, {%0,%1,%2,%3};"
                        : "+f"(c[0]), "+f"(c[1]), "+f"(c[2]), "+f"(c[3])
                        : "r"(af[mt][0]), "r"(af[mt][1]), "r"(af[mt][2]), "r"(af[mt][3]),
                          "r"(b0), "r"(b1));
                }
        }
        __syncthreads();
        s = s_n; k0v = k_n;
    }

    // ---- epilogue ----
#pragma unroll
    for (int mt = 0; mt < 2; mt++) {
        int r0 = m0 + wm * 32 + mt * 16 + g;
#pragma unroll
        for (int half = 0; half < 2; half++) {
            int row = r0 + half * 8;
            if (row >= M) continue;
#pragma unroll
            for (int nt = 0; nt < 8; nt++) {
                int col = n0 + wn * 64 + nt * 8 + 2 * tq;
                float* p = C + (size_t)row * Nc + col;
                float2 cv;
                cv.x = acc[mt][nt][half * 2 + 0];
                cv.y = acc[mt][nt][half * 2 + 1];
                if (accFlag) { float2 o = *(const float2*)p; cv.x += o.x; cv.y += o.y; }
                if (bias != nullptr) { cv.x += bias[col]; cv.y += bias[col + 1]; }
                if (reluFlag) { cv.x = fmaxf(cv.x, 0.f); cv.y = fmaxf(cv.y, 0.f); }
                if (roundFlag) { cv.x = rtf(cv.x); cv.y = rtf(cv.y); }
                *(float2*)p = cv;
            }
        }
    }
}

// ---------------- GAT: per-node attention logits ----------------
__global__ __launch_bounds__(256) void k_al(const float* __restrict__ aS,
                                            const float* __restrict__ aD) {
    int gw = (int)(((size_t)blockIdx.x * blockDim.x + threadIdx.x) >> 5);
    int lane = threadIdx.x & 31;
    if (gw >= NN * 2) return;
    int n = gw >> 1, k = gw & 1;
    const float* hp = g_h + (size_t)n * 512 + k * 256;
    const float* as = aS + k * 256;
    const float* ad = aD + k * 256;
    float ss = 0.f, sd = 0.f;
    for (int d2 = lane; d2 < 256; d2 += 32) {
        float hv = hp[d2];
        ss += hv * as[d2];
        sd += hv * ad[d2];
    }
#pragma unroll
    for (int o = 16; o; o >>= 1) {
        ss += __shfl_down_sync(0xffffffffu, ss, o);
        sd += __shfl_down_sync(0xffffffffu, sd, o);
    }
    if (lane == 0) { g_als[gw] = ss; g_ald[gw] = sd; }
}

// ---------------- GAT: single-pass online-softmax weighted gather ----------------
__global__ __launch_bounds__(256) void k_gat(const float* __restrict__ bias) {
    __shared__ float sW0[256], sW1[256];
    __shared__ int   sS[256];
    __shared__ float red[256];
    int n = blockIdx.x;
    int t = threadIdx.x;
    int base = g_rowstart[n], deg = g_deg[n];

    float ald0 = g_ald[2 * n], ald1 = g_ald[2 * n + 1];
    float m0 = lrelu(g_als[2 * n] + ald0);
    float m1 = lrelu(g_als[2 * n + 1] + ald1);
    float d0 = 1.f, d1 = 1.f;
    const float* hn = g_h + (size_t)n * 512;
    float a0 = hn[t];
    float a1 = hn[256 + t];

    for (int c0 = 0; c0 < deg; c0 += 256) {
        int cnt = min(256, deg - c0);
        float e0 = -1e30f, e1 = -1e30f;
        int sNode = 0;
        if (t < cnt) {
            sNode = g_es[base + c0 + t];
            e0 = lrelu(g_als[2 * sNode] + ald0);
            e1 = lrelu(g_als[2 * sNode + 1] + ald1);
        }
        red[t] = e0; __syncthreads();
        for (int o = 128; o; o >>= 1) { if (t < o) red[t] = fmaxf(red[t], red[t + o]); __syncthreads(); }
        float cm0 = red[0]; __syncthreads();
        red[t] = e1; __syncthreads();
        for (int o = 128; o; o >>= 1) { if (t < o) red[t] = fmaxf(red[t], red[t + o]); __syncthreads(); }
        float cm1 = red[0]; __syncthreads();

        float M0 = fmaxf(m0, cm0), M1 = fmaxf(m1, cm1);
        float sc0 = expf(m0 - M0), sc1 = expf(m1 - M1);
        a0 *= sc0; d0 *= sc0; m0 = M0;
        a1 *= sc1; d1 *= sc1; m1 = M1;

        if (t < cnt) {
            sS[t] = sNode;
            sW0[t] = expf(e0 - m0);
            sW1[t] = expf(e1 - m1);
        }
        __syncthreads();
        for (int j = 0; j < cnt; j++) {
            float w0 = sW0[j], w1 = sW1[j];
            const float* hs = g_h + (size_t)sS[j] * 512;
            a0 += w0 * hs[t];
            a1 += w1 * hs[256 + t];
            d0 += w0; d1 += w1;
        }
        __syncthreads();
    }
    float v = 0.5f * (a0 / fmaxf(d0, 1e-16f) + a1 / fmaxf(d1, 1e-16f)) + bias[t];
    g_xgat[(size_t)n * 256 + t] = rtf(fmaxf(v, 0.f));
}

// ---------------- RGCN gather (stores tf32-rounded) ----------------
__global__ __launch_bounds__(128) void k_rgcn() {
    int n = blockIdx.x;
    int c = threadIdx.x;
    int base = g_rowstart[n], deg = g_deg[n];
    float w0 = g_invcnt4[n * 4 + 0], w1 = g_invcnt4[n * 4 + 1];
    float w2 = g_invcnt4[n * 4 + 2], w3 = g_invcnt4[n * 4 + 3];
    float acc = 0.f;
#pragma unroll 2
    for (int j = 0; j < deg; j++) {
        int s = g_es[base + j];
        int r = g_etl[base + j];
        float w = (r == 0) ? w0 : (r == 1) ? w1 : (r == 2) ? w2 : w3;
        acc += w * g_xt[((size_t)r * NN + s) * EMBD + c];
    }
    g_xrgcn[(size_t)n * EMBD + c] = rtf(acc);
}

// ---------------- fold rgcn root into fusion weights, write transposed ----------------
__global__ void k_compose(const float* __restrict__ fW, const float* __restrict__ fB,
                          const float* __restrict__ Wroot, const float* __restrict__ rgcB,
                          float* __restrict__ btfus) {
    int b = blockIdx.x, t = threadIdx.x;   // 128 threads
    const float* F3 = fW + 512 * EMBD;
    if (b < HID) {
        float acc = fW[(256 + b) * EMBD + t];
        for (int h = 0; h < EMBD; h++)
            acc += Wroot[b * EMBD + h] * F3[h * EMBD + t];
        btfus[(size_t)t * 640 + 256 + b] = rtf(acc);
    } else {
        float acc = fB[t];
        for (int h = 0; h < EMBD; h++)
            acc += rgcB[h] * F3[h * EMBD + t];
        g_fb2[t] = acc;
    }
}

// ---------------- final L2 normalize ----------------
__global__ void k_norm(float* __restrict__ out) {
    int n = blockIdx.x;
    int t = threadIdx.x;   // 128 threads
    float v = out[(size_t)n * EMBD + t];
    float s = v * v;
#pragma unroll
    for (int o = 16; o; o >>= 1) s += __shfl_down_sync(0xffffffffu, s, o);
    __shared__ float sh[4];
    if ((t & 31) == 0) sh[t >> 5] = s;
    __syncthreads();
    float tot = sh[0] + sh[1] + sh[2] + sh[3];
    float nrm = fmaxf(sqrtf(tot), 1e-12f);
    out[(size_t)n * EMBD + t] = v / nrm;
}

// ---------------- host ----------------
static void launch_seg(const float* A0, int K0, const float* A1, int K1,
                       const float* A2, int K2, const float* Bt,
                       float* C, const float* bias, int M, int Nc,
                       int acc, int relu, int rnd,
                       int gz = 1, size_t zsB = 0, size_t zsC = 0) {
    dim3 grid(Nc / 128, (M + 127) / 128, gz);
    tgemm<<<grid, 256>>>(A0, K0, A1, K1, A2, K2, Bt, C, bias, M, Nc,
                         acc, relu, rnd, zsB, zsC);
}

extern "C" void kernel_launch(void* const* d_in, const int* in_sizes, int n_in,
                              void* d_out, int out_size) {
    const float* x    = (const float*)d_in[0];
    const int*   ei   = (const int*)d_in[1];
    const int*   et   = (const int*)d_in[2];
    const float* s1Wl = (const float*)d_in[3];
    const float* s1Wr = (const float*)d_in[4];
    const float* s1b  = (const float*)d_in[5];
    const float* s2Wl = (const float*)d_in[6];
    const float* s2Wr = (const float*)d_in[7];
    const float* s2b  = (const float*)d_in[8];
    const float* gatW = (const float*)d_in[9];
    const float* aSrc = (const float*)d_in[10];
    const float* aDst = (const float*)d_in[11];
    const float* gatB = (const float*)d_in[12];
    const float* Wrel = (const float*)d_in[13];
    const float* Wroot= (const float*)d_in[14];
    const float* rgcB = (const float*)d_in[15];
    const float* fW   = (const float*)d_in[16];
    const float* fB   = (const float*)d_in[17];
    float* out = (float*)d_out;

    const int* src = ei;
    const int* dst = ei + EE;

    float *p_xr, *p_agg1, *p_x1, *p_agg2, *p_xsage, *p_h, *p_xgat, *p_xt, *p_xrgcn, *p_fb2;
    float *p_bt1r, *p_bt1l, *p_bt2, *p_btg, *p_btrel, *p_btfus;
    cudaGetSymbolAddress((void**)&p_xr, g_xr);
    cudaGetSymbolAddress((void**)&p_agg1, g_agg1);
    cudaGetSymbolAddress((void**)&p_x1, g_x1);
    cudaGetSymbolAddress((void**)&p_agg2, g_agg2);
    cudaGetSymbolAddress((void**)&p_xsage, g_xsage);
    cudaGetSymbolAddress((void**)&p_h, g_h);
    cudaGetSymbolAddress((void**)&p_xgat, g_xgat);
    cudaGetSymbolAddress((void**)&p_xt, g_xt);
    cudaGetSymbolAddress((void**)&p_xrgcn, g_xrgcn);
    cudaGetSymbolAddress((void**)&p_fb2, g_fb2);
    cudaGetSymbolAddress((void**)&p_bt1r, g_bt1r);
    cudaGetSymbolAddress((void**)&p_bt1l, g_bt1l);
    cudaGetSymbolAddress((void**)&p_bt2, g_bt2);
    cudaGetSymbolAddress((void**)&p_btg, g_btg);
    cudaGetSymbolAddress((void**)&p_btrel, g_btrel);
    cudaGetSymbolAddress((void**)&p_btfus, g_btfus);

    // ---- setup (GEMM as 6th launch so ncu -s5 profiles it) ----
    k_zero_small<<<(NN * RR + 255) / 256, 256>>>();                             // 1
    k_count<<<(EE + 255) / 256, 256>>>(dst, et);                                // 2
    k_scan1<<<NBLK, 256>>>();                                                   // 3
    k_transB<<<(128 * 256 + 255) / 256, 256>>>(s1Wr, p_bt1r, 128, 256, 128, 0); // 4
    k_round4<<<(NN * IN_C / 4 + 255) / 256, 256>>>((const float4*)x, (float4*)p_xr,
                                                   NN * IN_C / 4);              // 5
    launch_seg(p_xr, IN_C, 0, 0, 0, 0, p_bt1r, p_x1, nullptr,
               NN, HID, 0, 0, 0);                                               // 6
    k_scan2<<<1, 256>>>();
    k_scan3_inv<<<NBLK, 256>>>();
    k_fill<<<(EE + 255) / 256, 256>>>(src, dst, et);

    // remaining weight transposes
    k_transB<<<(128 * 256 + 255) / 256, 256>>>(s1Wl, p_bt1l, 128, 256, 128, 0);
    k_transB<<<(256 * 256 + 255) / 256, 256>>>(s2Wl, p_bt2, 256, 256, 512, 0);
    k_transB<<<(256 * 256 + 255) / 256, 256>>>(s2Wr, p_bt2, 256, 256, 512, 256);
    k_transB<<<(256 * 512 + 255) / 256, 256>>>(gatW, p_btg, 256, 512, 256, 0);
    for (int r = 0; r < RR; r++)
        k_transB<<<(256 * 128 + 255) / 256, 256>>>(Wrel + (size_t)r * HID * EMBD,
                                                   p_btrel + (size_t)r * 128 * 256,
                                                   256, 128, 256, 0);
    k_transB<<<(256 * 128 + 255) / 256, 256>>>(fW, p_btfus, 256, 128, 640, 0);
    k_transB<<<(128 * 128 + 255) / 256, 256>>>(fW + 512 * EMBD, p_btfus, 128, 128, 640, 512);
    k_compose<<<HID + 1, EMBD>>>(fW, fB, Wroot, rgcB, p_btfus);

    // ---- SAGE 1 ----
    k_sage_gather<IN_C><<<NN, IN_C>>>(x, p_agg1);
    launch_seg(p_agg1, IN_C, 0, 0, 0, 0, p_bt1l, p_x1, s1b, NN, HID, 1, 1, 1);

    // ---- SAGE 2 (fused dual-A) ----
    k_sage_gather<HID><<<NN, HID>>>(p_x1, p_agg2);
    launch_seg(p_agg2, HID, p_x1, HID, 0, 0, p_bt2, p_xsage, s2b, NN, HID, 0, 1, 1);

    // ---- GAT ----
    launch_seg(p_xsage, HID, 0, 0, 0, 0, p_btg, p_h, nullptr, NN, 2 * HID, 0, 0, 0);
    k_al<<<(NN * 2 * 32 + 255) / 256, 256>>>(aSrc, aDst);
    k_gat<<<NN, 256>>>(gatB);

    // ---- RGCN (4 relations via grid.z) ----
    launch_seg(p_xgat, HID, 0, 0, 0, 0, p_btrel, p_xt, nullptr, NN, EMBD, 0, 0, 0,
               RR, (size_t)128 * 256, (size_t)NN * EMBD);
    k_rgcn<<<NN, 128>>>();

    // ---- Fusion (3-segment, rgcn-root folded) + normalize ----
    launch_seg(p_xsage, HID, p_xgat, HID, p_xrgcn, EMBD, p_btfus,
               out, p_fb2, NN, EMBD, 0, 0, 0);
    k_norm<<<NN, 128>>>(out);
}

// round 7
// speedup vs baseline: 2.4858x; 1.2229x over previous
#include <cuda_runtime.h>
#include <math.h>

#define NN   50000
#define EE   800000
#define IN_C 128
#define HID  256
#define EMBD 128
#define RR   4
#define NBLK ((NN + 255) / 256)

// ---------------- scratch (device globals; no allocation) ----------------
__device__ int      g_deg[NN];
__device__ float    g_invdeg[NN];
__device__ int      g_cnt4[NN * RR];
__device__ float    g_invcnt4[NN * RR];
__device__ int      g_rowstart[NN];
__device__ int      g_cursor[NN];
__device__ int      g_bsum[256];
__device__ int      g_boff[256];
__device__ int      g_es[EE];
__device__ int      g_etl[EE];
__device__ float    g_xr[(size_t)NN * IN_C];
__device__ float    g_agg1[(size_t)NN * IN_C];
__device__ float    g_x1[(size_t)NN * HID];
__device__ float    g_agg2[(size_t)NN * HID];
__device__ float    g_xsage[(size_t)NN * HID];
__device__ float    g_h[(size_t)NN * 2 * HID];
__device__ float    g_als[NN * 2];
__device__ float    g_ald[NN * 2];
__device__ float    g_xgat[(size_t)NN * HID];
__device__ float    g_xt[(size_t)RR * NN * EMBD];
__device__ float    g_xrgcn[(size_t)NN * EMBD];
__device__ float    g_fb2[EMBD];
__device__ float    g_bt1r[256 * 128];
__device__ float    g_bt1l[256 * 128];
__device__ float    g_bt2[256 * 512];
__device__ float    g_btg[512 * 256];
__device__ float    g_btrel[RR * 128 * 256];
__device__ float    g_btfus[128 * 640];

__device__ __forceinline__ float lrelu(float v) { return v > 0.f ? v : 0.2f * v; }

__device__ __forceinline__ unsigned f2tf32(float f) {
    unsigned r;
    asm("cvt.rna.tf32.f32 %0, %1;" : "=r"(r) : "f"(f));
    return r;
}
__device__ __forceinline__ float rtf(float f) { return __uint_as_float(f2tf32(f)); }

#define CP16(sm, gm) asm volatile("cp.async.cg.shared.global [%0], [%1], 16;" :: "r"(sm), "l"(gm))
#define CPCOMMIT()   asm volatile("cp.async.commit_group;")
#define CPWAIT(n)    asm volatile("cp.async.wait_group %0;" :: "n"(n))

// ---------------- zero / counts / scan / fill ----------------
__global__ void k_zero_small() {
    int i = blockIdx.x * blockDim.x + threadIdx.x;
    if (i < NN) { g_deg[i] = 0; g_cursor[i] = 0; }
    if (i < NN * RR) g_cnt4[i] = 0;
}

__global__ void k_count(const int* __restrict__ dst, const int* __restrict__ et) {
    int i = blockIdx.x * blockDim.x + threadIdx.x;
    if (i >= EE) return;
    int d = dst[i];
    atomicAdd(&g_deg[d], 1);
    atomicAdd(&g_cnt4[d * RR + et[i]], 1);
}

__global__ void k_scan1() {
    __shared__ int sh[256];
    int b = blockIdx.x, t = threadIdx.x;
    int i = b * 256 + t;
    int v = (i < NN) ? g_deg[i] : 0;
    sh[t] = v; __syncthreads();
    for (int o = 1; o < 256; o <<= 1) {
        int add = (t >= o) ? sh[t - o] : 0;
        __syncthreads();
        sh[t] += add;
        __syncthreads();
    }
    if (i < NN) g_rowstart[i] = sh[t] - v;
    if (t == 255) g_bsum[b] = sh[255];
}

__global__ void k_scan2() {
    __shared__ int sh[256];
    int t = threadIdx.x;
    int v = (t < NBLK) ? g_bsum[t] : 0;
    sh[t] = v; __syncthreads();
    for (int o = 1; o < 256; o <<= 1) {
        int add = (t >= o) ? sh[t - o] : 0;
        __syncthreads();
        sh[t] += add;
        __syncthreads();
    }
    g_boff[t] = sh[t] - v;
}

__global__ void k_scan3_inv() {
    int i = blockIdx.x * blockDim.x + threadIdx.x;
    if (i >= NN) return;
    g_rowstart[i] += g_boff[i >> 8];
    g_invdeg[i] = 1.f / fmaxf((float)g_deg[i], 1.f);
#pragma unroll
    for (int r = 0; r < RR; r++)
        g_invcnt4[i * RR + r] = 1.f / fmaxf((float)g_cnt4[i * RR + r], 1.f);
}

__global__ void k_fill(const int* __restrict__ src, const int* __restrict__ dst,
                       const int* __restrict__ et) {
    int e = blockIdx.x * blockDim.x + threadIdx.x;
    if (e >= EE) return;
    int d = dst[e];
    int pos = atomicAdd(&g_cursor[d], 1);
    int slot = g_rowstart[d] + pos;
    g_es[slot] = src[e];
    g_etl[slot] = et[e];
}

// ---------------- weight transpose (+tf32 round) ----------------
__global__ void k_transB(const float* __restrict__ B, float* __restrict__ Bt,
                         int K, int N, int ldBt, int kOff) {
    int i = blockIdx.x * blockDim.x + threadIdx.x;
    if (i >= K * N) return;
    int k = i / N, n = i % N;
    Bt[(size_t)n * ldBt + kOff + k] = rtf(B[(size_t)k * N + n]);
}

__global__ void k_round4(const float4* __restrict__ in, float4* __restrict__ out, int n4) {
    int i = blockIdx.x * blockDim.x + threadIdx.x;
    if (i >= n4) return;
    float4 v = in[i];
    v.x = rtf(v.x); v.y = rtf(v.y); v.z = rtf(v.z); v.w = rtf(v.w);
    out[i] = v;
}

// ---------------- SAGE mean-gather: 4 edge-groups x (D/4) float4 lanes ----------------
template <int D>
__global__ __launch_bounds__(D) void k_sage_gather(const float* __restrict__ xin,
                                                   float* __restrict__ agg) {
    constexpr int L = D / 4;
    __shared__ float4 sred[4][L];
    int n = blockIdx.x;
    int tid = threadIdx.x;
    int grp = tid / L, lane = tid % L;
    int base = g_rowstart[n], deg = g_deg[n];
    const float4* xin4 = (const float4*)xin;
    float4 acc = make_float4(0.f, 0.f, 0.f, 0.f);
    for (int j = grp; j < deg; j += 4) {
        int s = g_es[base + j];
        float4 v = xin4[(size_t)s * L + lane];
        acc.x += v.x; acc.y += v.y; acc.z += v.z; acc.w += v.w;
    }
    sred[grp][lane] = acc;
    __syncthreads();
    if (grp == 0) {
        float4 a = sred[0][lane], b = sred[1][lane], c = sred[2][lane], d = sred[3][lane];
        float w = g_invdeg[n];
        float4 o;
        o.x = rtf((a.x + b.x + c.x + d.x) * w);
        o.y = rtf((a.y + b.y + c.y + d.y) * w);
        o.z = rtf((a.z + b.z + c.z + d.z) * w);
        o.w = rtf((a.w + b.w + c.w + d.w) * w);
        ((float4*)agg)[(size_t)n * L + lane] = o;
    }
}

// ---------------- TF32 GEMM: 3-stage cp.async pipeline, multi-segment A ----------------
__global__ __launch_bounds__(256) void tgemm(
    const float* __restrict__ A0, int K0,
    const float* __restrict__ A1, int K1,
    const float* __restrict__ A2, int K2,
    const float* __restrict__ Bt,
    float* __restrict__ C, const float* __restrict__ bias,
    int M, int Nc, int accFlag, int reluFlag, int roundFlag,
    size_t zsB, size_t zsC) {
    extern __shared__ float sm[];
    float* smA = sm;               // 3 * 2560 floats
    float* smB = sm + 3 * 2560;
#define ASX(st, r, c) smA[(st) * 2560 + (r) * 20 + (c)]
#define BSX(st, r, c) smB[(st) * 2560 + (r) * 20 + (c)]
    const int tid = threadIdx.x;
    const int m0 = blockIdx.y * 128, n0 = blockIdx.x * 128;
    const int wid = tid >> 5, lane = tid & 31;
    const int wm = wid & 3, wn = wid >> 2;
    const int g = lane >> 2, tq = lane & 3;
    const int Ktot = K0 + K1 + K2;
    Bt += blockIdx.z * zsB;
    C  += blockIdx.z * zsC;
    const float* segA[3] = {A0, A1, A2};
    const int segK01 = K0 + K1;
    const int T = Ktot >> 4;

    float acc[2][8][4];
#pragma unroll
    for (int mt = 0; mt < 2; mt++)
#pragma unroll
        for (int nt = 0; nt < 8; nt++)
#pragma unroll
            for (int r = 0; r < 4; r++) acc[mt][nt][r] = 0.f;

    const int aRow = tid >> 1;
    const int aCol = (tid & 1) * 8;
    const bool aValid = (m0 + aRow) < M;
    const int aR = aValid ? (m0 + aRow) : 0;
    const float* BtRow = Bt + (size_t)(n0 + aRow) * Ktot + aCol;

    const int aLr = (lane & 7) + (((lane >> 3) & 1) << 3);
    const int aLc = ((lane >> 4) & 1) * 4;
    const int bLr = (lane & 7) + (((lane >> 4) & 1) << 3);
    const int bLc = ((lane >> 3) & 1) * 4;

    auto issue = [&](int tile, int buf) {
        int kpos = tile * 16;
        int s, kk;
        if (kpos < K0) { s = 0; kk = kpos; }
        else if (kpos < segK01) { s = 1; kk = kpos - K0; }
        else { s = 2; kk = kpos - segK01; }
        int Ks = (s == 0) ? K0 : (s == 1) ? K1 : K2;
        const float* Ag = segA[s] + (size_t)aR * Ks + kk + aCol;
        unsigned sa = (unsigned)__cvta_generic_to_shared(&ASX(buf, aRow, aCol));
        CP16(sa, Ag); CP16(sa + 16, Ag + 4);
        const float* Bg = BtRow + kpos;
        unsigned sb = (unsigned)__cvta_generic_to_shared(&BSX(buf, aRow, aCol));
        CP16(sb, Bg); CP16(sb + 16, Bg + 4);
    };

    // prologue: issue tiles 0,1
    for (int p = 0; p < 2 && p < T; p++) { issue(p, p); CPCOMMIT(); }

    for (int t = 0; t < T; t++) {
        CPWAIT(1);
        __syncthreads();
        if (t + 2 < T) issue(t + 2, (t + 2) % 3);
        CPCOMMIT();
        const int pb = t % 3;
#pragma unroll
        for (int ks = 0; ks < 16; ks += 8) {
            unsigned af[2][4], bf[4][4];
#pragma unroll
            for (int mt = 0; mt < 2; mt++) {
                unsigned addr = (unsigned)__cvta_generic_to_shared(
                    &ASX(pb, wm * 32 + mt * 16 + aLr, ks + aLc));
                asm volatile("ldmatrix.sync.aligned.m8n8.x4.shared.b16 {%0,%1,%2,%3}, [%4];"
                    : "=r"(af[mt][0]), "=r"(af[mt][1]), "=r"(af[mt][2]), "=r"(af[mt][3])
                    : "r"(addr));
            }
#pragma unroll
            for (int np = 0; np < 4; np++) {
                unsigned addr = (unsigned)__cvta_generic_to_shared(
                    &BSX(pb, wn * 64 + np * 16 + bLr, ks + bLc));
                asm volatile("ldmatrix.sync.aligned.m8n8.x4.shared.b16 {%0,%1,%2,%3}, [%4];"
                    : "=r"(bf[np][0]), "=r"(bf[np][1]), "=r"(bf[np][2]), "=r"(bf[np][3])
                    : "r"(addr));
            }
#pragma unroll
            for (int mt = 0; mt < 2; mt++)
#pragma unroll
                for (int nt = 0; nt < 8; nt++) {
                    unsigned b0 = bf[nt >> 1][(nt & 1) * 2 + 0];
                    unsigned b1 = bf[nt >> 1][(nt & 1) * 2 + 1];
                    float* c = acc[mt][nt];
                    asm volatile(
                        "mma.sync.aligned.m16n8k8.row.col.f32.tf32.tf32.f32 "
                        "{%0,%1,%2,%3}, {%4,%5,%6,%7}, {%8,%9}, {%0,%1,%2,%3};"
                        : "+f"(c[0]), "+f"(c[1]), "+f"(c[2]), "+f"(c[3])
                        : "r"(af[mt][0]), "r"(af[mt][1]), "r"(af[mt][2]), "r"(af[mt][3]),
                          "r"(b0), "r"(b1));
                }
        }
        __syncthreads();
    }

#pragma unroll
    for (int mt = 0; mt < 2; mt++) {
        int r0 = m0 + wm * 32 + mt * 16 + g;
#pragma unroll
        for (int half = 0; half < 2; half++) {
            int row = r0 + half * 8;
            if (row >= M) continue;
#pragma unroll
            for (int nt = 0; nt < 8; nt++) {
                int col = n0 + wn * 64 + nt * 8 + 2 * tq;
                float* p = C + (size_t)row * Nc + col;
                float2 cv;
                cv.x = acc[mt][nt][half * 2 + 0];
                cv.y = acc[mt][nt][half * 2 + 1];
                if (accFlag) { float2 o = *(const float2*)p; cv.x += o.x; cv.y += o.y; }
                if (bias != nullptr) { cv.x += bias[col]; cv.y += bias[col + 1]; }
                if (reluFlag) { cv.x = fmaxf(cv.x, 0.f); cv.y = fmaxf(cv.y, 0.f); }
                if (roundFlag) { cv.x = rtf(cv.x); cv.y = rtf(cv.y); }
                *(float2*)p = cv;
            }
        }
    }
#undef ASX
#undef BSX
}

// ---------------- GAT: per-node attention logits (float4) ----------------
__global__ __launch_bounds__(256) void k_al(const float* __restrict__ aS,
                                            const float* __restrict__ aD) {
    int gw = (int)(((size_t)blockIdx.x * blockDim.x + threadIdx.x) >> 5);
    int lane = threadIdx.x & 31;
    if (gw >= NN * 2) return;
    int n = gw >> 1, k = gw & 1;
    const float4* hp = (const float4*)(g_h + (size_t)n * 512 + k * 256);
    const float4* as4 = (const float4*)(aS + k * 256);
    const float4* ad4 = (const float4*)(aD + k * 256);
    float ss = 0.f, sd = 0.f;
#pragma unroll
    for (int it = 0; it < 2; it++) {
        int j = lane + it * 32;
        float4 h = hp[j], A = as4[j], D = ad4[j];
        ss += h.x * A.x + h.y * A.y + h.z * A.z + h.w * A.w;
        sd += h.x * D.x + h.y * D.y + h.z * D.z + h.w * D.w;
    }
#pragma unroll
    for (int o = 16; o; o >>= 1) {
        ss += __shfl_down_sync(0xffffffffu, ss, o);
        sd += __shfl_down_sync(0xffffffffu, sd, o);
    }
    if (lane == 0) { g_als[gw] = ss; g_ald[gw] = sd; }
}

// ---------------- GAT: online-softmax, thread owns float2 of features ----------------
__global__ __launch_bounds__(256) void k_gat(const float* __restrict__ bias) {
    __shared__ float sW0[256], sW1[256];
    __shared__ int   sS[256];
    __shared__ float wm0[8], wm1[8];
    __shared__ float2 stage[128];
    int n = blockIdx.x;
    int t = threadIdx.x;
    int lane = t & 31, warp = t >> 5;
    int base = g_rowstart[n], deg = g_deg[n];

    float ald0 = g_ald[2 * n], ald1 = g_ald[2 * n + 1];
    float m0 = lrelu(g_als[2 * n] + ald0);
    float m1 = lrelu(g_als[2 * n + 1] + ald1);
    float d0 = 1.f, d1 = 1.f;
    const float2* h2 = (const float2*)g_h;     // row = 256 float2
    float2 a = h2[(size_t)n * 256 + t];
    bool head0 = (t < 128);

    for (int c0 = 0; c0 < deg; c0 += 256) {
        int cnt = min(256, deg - c0);
        float e0 = -1e30f, e1 = -1e30f;
        int sNode = 0;
        if (t < cnt) {
            sNode = g_es[base + c0 + t];
            e0 = lrelu(g_als[2 * sNode] + ald0);
            e1 = lrelu(g_als[2 * sNode + 1] + ald1);
        }
        // warp max then cross-warp via shared
        float w0r = e0, w1r = e1;
#pragma unroll
        for (int o = 16; o; o >>= 1) {
            w0r = fmaxf(w0r, __shfl_xor_sync(0xffffffffu, w0r, o));
            w1r = fmaxf(w1r, __shfl_xor_sync(0xffffffffu, w1r, o));
        }
        if (lane == 0) { wm0[warp] = w0r; wm1[warp] = w1r; }
        __syncthreads();
        float cm0 = wm0[0], cm1 = wm1[0];
#pragma unroll
        for (int w = 1; w < 8; w++) { cm0 = fmaxf(cm0, wm0[w]); cm1 = fmaxf(cm1, wm1[w]); }

        float M0 = fmaxf(m0, cm0), M1 = fmaxf(m1, cm1);
        float sc0 = expf(m0 - M0), sc1 = expf(m1 - M1);
        float scMe = head0 ? sc0 : sc1;
        a.x *= scMe; a.y *= scMe;
        d0 *= sc0; d1 *= sc1; m0 = M0; m1 = M1;

        if (t < cnt) {
            sS[t] = sNode;
            sW0[t] = expf(e0 - m0);
            sW1[t] = expf(e1 - m1);
        }
        __syncthreads();
        for (int j = 0; j < cnt; j++) {
            float w0 = sW0[j], w1 = sW1[j];
            float w = head0 ? w0 : w1;
            float2 hv = h2[(size_t)sS[j] * 256 + t];
            a.x += w * hv.x; a.y += w * hv.y;
            d0 += w0; d1 += w1;
        }
        __syncthreads();
    }
    float i0 = 1.f / fmaxf(d0, 1e-16f), i1 = 1.f / fmaxf(d1, 1e-16f);
    if (!head0) stage[t - 128] = a;
    __syncthreads();
    if (head0) {
        float2 b1 = stage[t];
        float v0 = 0.5f * (a.x * i0 + b1.x * i1) + bias[2 * t];
        float v1 = 0.5f * (a.y * i0 + b1.y * i1) + bias[2 * t + 1];
        float2 o;
        o.x = rtf(fmaxf(v0, 0.f));
        o.y = rtf(fmaxf(v1, 0.f));
        ((float2*)g_xgat)[(size_t)n * 128 + t] = o;
    }
}

// ---------------- RGCN gather: 4 edge-groups x 32 float4 lanes ----------------
__global__ __launch_bounds__(128) void k_rgcn() {
    __shared__ float4 sred[4][32];
    int n = blockIdx.x;
    int t = threadIdx.x;
    int grp = t >> 5, lane = t & 31;
    int base = g_rowstart[n], deg = g_deg[n];
    float w0 = g_invcnt4[n * 4 + 0], w1 = g_invcnt4[n * 4 + 1];
    float w2 = g_invcnt4[n * 4 + 2], w3 = g_invcnt4[n * 4 + 3];
    const float4* xt4 = (const float4*)g_xt;
    float4 acc = make_float4(0.f, 0.f, 0.f, 0.f);
    for (int j = grp; j < deg; j += 4) {
        int s = g_es[base + j];
        int r = g_etl[base + j];
        float w = (r == 0) ? w0 : (r == 1) ? w1 : (r == 2) ? w2 : w3;
        float4 v = xt4[((size_t)r * NN + s) * 32 + lane];
        acc.x += w * v.x; acc.y += w * v.y; acc.z += w * v.z; acc.w += w * v.w;
    }
    sred[grp][lane] = acc;
    __syncthreads();
    if (grp == 0) {
        float4 A = sred[0][lane], B = sred[1][lane], C = sred[2][lane], D = sred[3][lane];
        float4 o;
        o.x = rtf(A.x + B.x + C.x + D.x);
        o.y = rtf(A.y + B.y + C.y + D.y);
        o.z = rtf(A.z + B.z + C.z + D.z);
        o.w = rtf(A.w + B.w + C.w + D.w);
        ((float4*)g_xrgcn)[(size_t)n * 32 + lane] = o;
    }
}

// ---------------- fold rgcn root into fusion weights ----------------
__global__ void k_compose(const float* __restrict__ fW, const float* __restrict__ fB,
                          const float* __restrict__ Wroot, const float* __restrict__ rgcB,
                          float* __restrict__ btfus) {
    int b = blockIdx.x, t = threadIdx.x;
    const float* F3 = fW + 512 * EMBD;
    if (b < HID) {
        float acc = fW[(256 + b) * EMBD + t];
        for (int h = 0; h < EMBD; h++)
            acc += Wroot[b * EMBD + h] * F3[h * EMBD + t];
        btfus[(size_t)t * 640 + 256 + b] = rtf(acc);
    } else {
        float acc = fB[t];
        for (int h = 0; h < EMBD; h++)
            acc += rgcB[h] * F3[h * EMBD + t];
        g_fb2[t] = acc;
    }
}

// ---------------- final L2 normalize ----------------
__global__ void k_norm(float* __restrict__ out) {
    int n = blockIdx.x;
    int t = threadIdx.x;
    float v = out[(size_t)n * EMBD + t];
    float s = v * v;
#pragma unroll
    for (int o = 16; o; o >>= 1) s += __shfl_down_sync(0xffffffffu, s, o);
    __shared__ float sh[4];
    if ((t & 31) == 0) sh[t >> 5] = s;
    __syncthreads();
    float tot = sh[0] + sh[1] + sh[2] + sh[3];
    float nrm = fmaxf(sqrtf(tot), 1e-12f);
    out[(size_t)n * EMBD + t] = v / nrm;
}

// ---------------- host ----------------
#define TG_SMEM (3 * 2 * 2560 * 4)

static void launch_seg(const float* A0, int K0, const float* A1, int K1,
                       const float* A2, int K2, const float* Bt,
                       float* C, const float* bias, int M, int Nc,
                       int acc, int relu, int rnd,
                       int gz = 1, size_t zsB = 0, size_t zsC = 0) {
    dim3 grid(Nc / 128, (M + 127) / 128, gz);
    tgemm<<<grid, 256, TG_SMEM>>>(A0, K0, A1, K1, A2, K2, Bt, C, bias, M, Nc,
                                  acc, relu, rnd, zsB, zsC);
}

extern "C" void kernel_launch(void* const* d_in, const int* in_sizes, int n_in,
                              void* d_out, int out_size) {
    const float* x    = (const float*)d_in[0];
    const int*   ei   = (const int*)d_in[1];
    const int*   et   = (const int*)d_in[2];
    const float* s1Wl = (const float*)d_in[3];
    const float* s1Wr = (const float*)d_in[4];
    const float* s1b  = (const float*)d_in[5];
    const float* s2Wl = (const float*)d_in[6];
    const float* s2Wr = (const float*)d_in[7];
    const float* s2b  = (const float*)d_in[8];
    const float* gatW = (const float*)d_in[9];
    const float* aSrc = (const float*)d_in[10];
    const float* aDst = (const float*)d_in[11];
    const float* gatB = (const float*)d_in[12];
    const float* Wrel = (const float*)d_in[13];
    const float* Wroot= (const float*)d_in[14];
    const float* rgcB = (const float*)d_in[15];
    const float* fW   = (const float*)d_in[16];
    const float* fB   = (const float*)d_in[17];
    float* out = (float*)d_out;

    const int* src = ei;
    const int* dst = ei + EE;

    cudaFuncSetAttribute(tgemm, cudaFuncAttributeMaxDynamicSharedMemorySize, TG_SMEM);

    float *p_xr, *p_agg1, *p_x1, *p_agg2, *p_xsage, *p_h, *p_xgat, *p_xt, *p_xrgcn, *p_fb2;
    float *p_bt1r, *p_bt1l, *p_bt2, *p_btg, *p_btrel, *p_btfus;
    cudaGetSymbolAddress((void**)&p_xr, g_xr);
    cudaGetSymbolAddress((void**)&p_agg1, g_agg1);
    cudaGetSymbolAddress((void**)&p_x1, g_x1);
    cudaGetSymbolAddress((void**)&p_agg2, g_agg2);
    cudaGetSymbolAddress((void**)&p_xsage, g_xsage);
    cudaGetSymbolAddress((void**)&p_h, g_h);
    cudaGetSymbolAddress((void**)&p_xgat, g_xgat);
    cudaGetSymbolAddress((void**)&p_xt, g_xt);
    cudaGetSymbolAddress((void**)&p_xrgcn, g_xrgcn);
    cudaGetSymbolAddress((void**)&p_fb2, g_fb2);
    cudaGetSymbolAddress((void**)&p_bt1r, g_bt1r);
    cudaGetSymbolAddress((void**)&p_bt1l, g_bt1l);
    cudaGetSymbolAddress((void**)&p_bt2, g_bt2);
    cudaGetSymbolAddress((void**)&p_btg, g_btg);
    cudaGetSymbolAddress((void**)&p_btrel, g_btrel);
    cudaGetSymbolAddress((void**)&p_btfus, g_btfus);

    // launches 1-4 (observed: ncu profiles launch #4 -> make it a GEMM)
    k_zero_small<<<(NN * RR + 255) / 256, 256>>>();                             // 1
    k_transB<<<(128 * 256 + 255) / 256, 256>>>(s1Wr, p_bt1r, 128, 256, 128, 0); // 2
    k_round4<<<(NN * IN_C / 4 + 255) / 256, 256>>>((const float4*)x, (float4*)p_xr,
                                                   NN * IN_C / 4);              // 3
    launch_seg(p_xr, IN_C, 0, 0, 0, 0, p_bt1r, p_x1, nullptr,
               NN, HID, 0, 0, 0);                                               // 4

    // CSR build
    k_count<<<(EE + 255) / 256, 256>>>(dst, et);
    k_scan1<<<NBLK, 256>>>();
    k_scan2<<<1, 256>>>();
    k_scan3_inv<<<NBLK, 256>>>();
    k_fill<<<(EE + 255) / 256, 256>>>(src, dst, et);

    // remaining weight transposes
    k_transB<<<(128 * 256 + 255) / 256, 256>>>(s1Wl, p_bt1l, 128, 256, 128, 0);
    k_transB<<<(256 * 256 + 255) / 256, 256>>>(s2Wl, p_bt2, 256, 256, 512, 0);
    k_transB<<<(256 * 256 + 255) / 256, 256>>>(s2Wr, p_bt2, 256, 256, 512, 256);
    k_transB<<<(256 * 512 + 255) / 256, 256>>>(gatW, p_btg, 256, 512, 256, 0);
    for (int r = 0; r < RR; r++)
        k_transB<<<(256 * 128 + 255) / 256, 256>>>(Wrel + (size_t)r * HID * EMBD,
                                                   p_btrel + (size_t)r * 128 * 256,
                                                   256, 128, 256, 0);
    k_transB<<<(256 * 128 + 255) / 256, 256>>>(fW, p_btfus, 256, 128, 640, 0);
    k_transB<<<(128 * 128 + 255) / 256, 256>>>(fW + 512 * EMBD, p_btfus, 128, 128, 640, 512);
    k_compose<<<HID + 1, EMBD>>>(fW, fB, Wroot, rgcB, p_btfus);

    // ---- SAGE 1 ----
    k_sage_gather<IN_C><<<NN, IN_C>>>(x, p_agg1);
    launch_seg(p_agg1, IN_C, 0, 0, 0, 0, p_bt1l, p_x1, s1b, NN, HID, 1, 1, 1);

    // ---- SAGE 2 ----
    k_sage_gather<HID><<<NN, HID>>>(p_x1, p_agg2);
    launch_seg(p_agg2, HID, p_x1, HID, 0, 0, p_bt2, p_xsage, s2b, NN, HID, 0, 1, 1);

    // ---- GAT ----
    launch_seg(p_xsage, HID, 0, 0, 0, 0, p_btg, p_h, nullptr, NN, 2 * HID, 0, 0, 0);
    k_al<<<(NN * 2 * 32 + 255) / 256, 256>>>(aSrc, aDst);
    k_gat<<<NN, 256>>>(gatB);

    // ---- RGCN ----
    launch_seg(p_xgat, HID, 0, 0, 0, 0, p_btrel, p_xt, nullptr, NN, EMBD, 0, 0, 0,
               RR, (size_t)128 * 256, (size_t)NN * EMBD);
    k_rgcn<<<NN, 128>>>();

    // ---- Fusion + normalize ----
    launch_seg(p_xsage, HID, p_xgat, HID, p_xrgcn, EMBD, p_btfus,
               out, p_fb2, NN, EMBD, 0, 0, 0);
    k_norm<<<NN, 128>>>(out);
}

// round 8
// speedup vs baseline: 2.5851x; 1.0399x over previous
#include <cuda_runtime.h>
#include <math.h>

#define NN   50000
#define EE   800000
#define IN_C 128
#define HID  256
#define EMBD 128
#define RR   4
#define NBLK ((NN + 255) / 256)

// ---------------- scratch (device globals; no allocation) ----------------
__device__ int      g_deg[NN];
__device__ float    g_invdeg[NN];
__device__ int      g_cnt4[NN * RR];
__device__ float    g_invcnt4[NN * RR];
__device__ int      g_rowstart[NN];
__device__ int      g_cursor[NN];
__device__ int      g_bsum[256];
__device__ int      g_boff[256];
__device__ int      g_es[EE];
__device__ int      g_etl[EE];
__device__ float    g_xr[(size_t)NN * IN_C];
__device__ float    g_agg1[(size_t)NN * IN_C];
__device__ float    g_x1[(size_t)NN * HID];
__device__ float    g_agg2[(size_t)NN * HID];
__device__ float    g_xsage[(size_t)NN * HID];
__device__ float    g_h[(size_t)NN * 2 * HID];
__device__ float    g_als[NN * 2];
__device__ float    g_ald[NN * 2];
__device__ float    g_xgat[(size_t)NN * HID];
__device__ float    g_xt[(size_t)RR * NN * EMBD];
__device__ float    g_xrgcn[(size_t)NN * EMBD];
__device__ float    g_fb2[EMBD];
__device__ float    g_bt1r[256 * 128];
__device__ float    g_bt1l[256 * 128];
__device__ float    g_bt2[256 * 512];
__device__ float    g_btg[512 * 256];
__device__ float    g_btrel[RR * 128 * 256];
__device__ float    g_btfus[128 * 640];

__device__ __forceinline__ float lrelu(float v) { return v > 0.f ? v : 0.2f * v; }

__device__ __forceinline__ unsigned f2tf32(float f) {
    unsigned r;
    asm("cvt.rna.tf32.f32 %0, %1;" : "=r"(r) : "f"(f));
    return r;
}
__device__ __forceinline__ float rtf(float f) { return __uint_as_float(f2tf32(f)); }

#define CP16(sm, gm) asm volatile("cp.async.cg.shared.global [%0], [%1], 16;" :: "r"(sm), "l"(gm))
#define CPCOMMIT()   asm volatile("cp.async.commit_group;")
#define CPWAIT(n)    asm volatile("cp.async.wait_group %0;" :: "n"(n))

// ---------------- zero / counts / scan / fill ----------------
__global__ void k_zero_small() {
    int i = blockIdx.x * blockDim.x + threadIdx.x;
    if (i < NN) { g_deg[i] = 0; g_cursor[i] = 0; }
    if (i < NN * RR) g_cnt4[i] = 0;
}

__global__ void k_count(const int* __restrict__ dst, const int* __restrict__ et) {
    int i = blockIdx.x * blockDim.x + threadIdx.x;
    if (i >= EE) return;
    int d = dst[i];
    atomicAdd(&g_deg[d], 1);
    atomicAdd(&g_cnt4[d * RR + et[i]], 1);
}

__global__ void k_scan1() {
    __shared__ int sh[256];
    int b = blockIdx.x, t = threadIdx.x;
    int i = b * 256 + t;
    int v = (i < NN) ? g_deg[i] : 0;
    sh[t] = v; __syncthreads();
    for (int o = 1; o < 256; o <<= 1) {
        int add = (t >= o) ? sh[t - o] : 0;
        __syncthreads();
        sh[t] += add;
        __syncthreads();
    }
    if (i < NN) g_rowstart[i] = sh[t] - v;
    if (t == 255) g_bsum[b] = sh[255];
}

__global__ void k_scan2() {
    __shared__ int sh[256];
    int t = threadIdx.x;
    int v = (t < NBLK) ? g_bsum[t] : 0;
    sh[t] = v; __syncthreads();
    for (int o = 1; o < 256; o <<= 1) {
        int add = (t >= o) ? sh[t - o] : 0;
        __syncthreads();
        sh[t] += add;
        __syncthreads();
    }
    g_boff[t] = sh[t] - v;
}

__global__ void k_scan3_inv() {
    int i = blockIdx.x * blockDim.x + threadIdx.x;
    if (i >= NN) return;
    g_rowstart[i] += g_boff[i >> 8];
    g_invdeg[i] = 1.f / fmaxf((float)g_deg[i], 1.f);
#pragma unroll
    for (int r = 0; r < RR; r++)
        g_invcnt4[i * RR + r] = 1.f / fmaxf((float)g_cnt4[i * RR + r], 1.f);
}

__global__ void k_fill(const int* __restrict__ src, const int* __restrict__ dst,
                       const int* __restrict__ et) {
    int e = blockIdx.x * blockDim.x + threadIdx.x;
    if (e >= EE) return;
    int d = dst[e];
    int pos = atomicAdd(&g_cursor[d], 1);
    int slot = g_rowstart[d] + pos;
    g_es[slot] = src[e];
    g_etl[slot] = et[e];
}

// ---------------- weight transpose (+tf32 round) ----------------
__global__ void k_transB(const float* __restrict__ B, float* __restrict__ Bt,
                         int K, int N, int ldBt, int kOff) {
    int i = blockIdx.x * blockDim.x + threadIdx.x;
    if (i >= K * N) return;
    int k = i / N, n = i % N;
    Bt[(size_t)n * ldBt + kOff + k] = rtf(B[(size_t)k * N + n]);
}

// batched transpose: all remaining weights in one launch
struct TSeg { const float* B; float* Bt; int K; int N; int ldBt; int kOff; };
struct TSegs { TSeg s[10]; };

__global__ void k_transAll(TSegs P) {
    TSeg sg = P.s[blockIdx.y];
    int i = blockIdx.x * blockDim.x + threadIdx.x;
    if (i >= sg.K * sg.N) return;
    int k = i / sg.N, n = i % sg.N;
    sg.Bt[(size_t)n * sg.ldBt + sg.kOff + k] = rtf(sg.B[(size_t)k * sg.N + n]);
}

__global__ void k_round4(const float4* __restrict__ in, float4* __restrict__ out, int n4) {
    int i = blockIdx.x * blockDim.x + threadIdx.x;
    if (i >= n4) return;
    float4 v = in[i];
    v.x = rtf(v.x); v.y = rtf(v.y); v.z = rtf(v.z); v.w = rtf(v.w);
    out[i] = v;
}

// ---------------- SAGE mean-gather: 4 edge-groups x (D/4) float4 lanes ----------------
template <int D>
__global__ __launch_bounds__(D) void k_sage_gather(const float* __restrict__ xin,
                                                   float* __restrict__ agg) {
    constexpr int L = D / 4;
    __shared__ float4 sred[4][L];
    int n = blockIdx.x;
    int tid = threadIdx.x;
    int grp = tid / L, lane = tid % L;
    int base = g_rowstart[n], deg = g_deg[n];
    const float4* xin4 = (const float4*)xin;
    float4 acc = make_float4(0.f, 0.f, 0.f, 0.f);
    for (int j = grp; j < deg; j += 4) {
        int s = g_es[base + j];
        float4 v = xin4[(size_t)s * L + lane];
        acc.x += v.x; acc.y += v.y; acc.z += v.z; acc.w += v.w;
    }
    sred[grp][lane] = acc;
    __syncthreads();
    if (grp == 0) {
        float4 a = sred[0][lane], b = sred[1][lane], c = sred[2][lane], d = sred[3][lane];
        float w = g_invdeg[n];
        float4 o;
        o.x = rtf((a.x + b.x + c.x + d.x) * w);
        o.y = rtf((a.y + b.y + c.y + d.y) * w);
        o.z = rtf((a.z + b.z + c.z + d.z) * w);
        o.w = rtf((a.w + b.w + c.w + d.w) * w);
        ((float4*)agg)[(size_t)n * L + lane] = o;
    }
}

// ---------------- TF32 GEMM: 4-stage cp.async pipeline, 1 sync/tile ----------------
__global__ __launch_bounds__(256) void tgemm(
    const float* __restrict__ A0, int K0,
    const float* __restrict__ A1, int K1,
    const float* __restrict__ A2, int K2,
    const float* __restrict__ Bt,
    float* __restrict__ C, const float* __restrict__ bias,
    int M, int Nc, int accFlag, int reluFlag, int roundFlag,
    size_t zsB, size_t zsC) {
    extern __shared__ float sm[];
    float* smA = sm;               // 4 * 2560 floats
    float* smB = sm + 4 * 2560;
#define ASX(st, r, c) smA[(st) * 2560 + (r) * 20 + (c)]
#define BSX(st, r, c) smB[(st) * 2560 + (r) * 20 + (c)]
    const int tid = threadIdx.x;
    const int m0 = blockIdx.y * 128, n0 = blockIdx.x * 128;
    const int wid = tid >> 5, lane = tid & 31;
    const int wm = wid & 3, wn = wid >> 2;
    const int g = lane >> 2, tq = lane & 3;
    const int Ktot = K0 + K1 + K2;
    Bt += blockIdx.z * zsB;
    C  += blockIdx.z * zsC;
    const float* segA[3] = {A0, A1, A2};
    const int segK01 = K0 + K1;
    const int T = Ktot >> 4;

    float acc[2][8][4];
#pragma unroll
    for (int mt = 0; mt < 2; mt++)
#pragma unroll
        for (int nt = 0; nt < 8; nt++)
#pragma unroll
            for (int r = 0; r < 4; r++) acc[mt][nt][r] = 0.f;

    const int aRow = tid >> 1;
    const int aCol = (tid & 1) * 8;
    const bool aValid = (m0 + aRow) < M;
    const int aR = aValid ? (m0 + aRow) : 0;
    const float* BtRow = Bt + (size_t)(n0 + aRow) * Ktot + aCol;

    const int aLr = (lane & 7) + (((lane >> 3) & 1) << 3);
    const int aLc = ((lane >> 4) & 1) * 4;
    const int bLr = (lane & 7) + (((lane >> 4) & 1) << 3);
    const int bLc = ((lane >> 3) & 1) * 4;

    auto issue = [&](int tile, int buf) {
        int kpos = tile * 16;
        int s, kk;
        if (kpos < K0) { s = 0; kk = kpos; }
        else if (kpos < segK01) { s = 1; kk = kpos - K0; }
        else { s = 2; kk = kpos - segK01; }
        int Ks = (s == 0) ? K0 : (s == 1) ? K1 : K2;
        const float* Ag = segA[s] + (size_t)aR * Ks + kk + aCol;
        unsigned sa = (unsigned)__cvta_generic_to_shared(&ASX(buf, aRow, aCol));
        CP16(sa, Ag); CP16(sa + 16, Ag + 4);
        const float* Bg = BtRow + kpos;
        unsigned sb = (unsigned)__cvta_generic_to_shared(&BSX(buf, aRow, aCol));
        CP16(sb, Bg); CP16(sb + 16, Bg + 4);
    };

    // prologue: issue tiles 0,1,2
    for (int p = 0; p < 3 && p < T; p++) { issue(p, p); CPCOMMIT(); }

    for (int t = 0; t < T; t++) {
        CPWAIT(2);
        __syncthreads();          // single barrier per tile
        if (t + 3 < T) issue(t + 3, (t + 3) & 3);
        CPCOMMIT();
        const int pb = t & 3;
#pragma unroll
        for (int ks = 0; ks < 16; ks += 8) {
            unsigned af[2][4], bf[4][4];
#pragma unroll
            for (int mt = 0; mt < 2; mt++) {
                unsigned addr = (unsigned)__cvta_generic_to_shared(
                    &ASX(pb, wm * 32 + mt * 16 + aLr, ks + aLc));
                asm volatile("ldmatrix.sync.aligned.m8n8.x4.shared.b16 {%0,%1,%2,%3}, [%4];"
                    : "=r"(af[mt][0]), "=r"(af[mt][1]), "=r"(af[mt][2]), "=r"(af[mt][3])
                    : "r"(addr));
            }
#pragma unroll
            for (int np = 0; np < 4; np++) {
                unsigned addr = (unsigned)__cvta_generic_to_shared(
                    &BSX(pb, wn * 64 + np * 16 + bLr, ks + bLc));
                asm volatile("ldmatrix.sync.aligned.m8n8.x4.shared.b16 {%0,%1,%2,%3}, [%4];"
                    : "=r"(bf[np][0]), "=r"(bf[np][1]), "=r"(bf[np][2]), "=r"(bf[np][3])
                    : "r"(addr));
            }
#pragma unroll
            for (int mt = 0; mt < 2; mt++)
#pragma unroll
                for (int nt = 0; nt < 8; nt++) {
                    unsigned b0 = bf[nt >> 1][(nt & 1) * 2 + 0];
                    unsigned b1 = bf[nt >> 1][(nt & 1) * 2 + 1];
                    float* c = acc[mt][nt];
                    asm volatile(
                        "mma.sync.aligned.m16n8k8.row.col.f32.tf32.tf32.f32 "
                        "{%0,%1,%2,%3}, {%4,%5,%6,%7}, {%8,%9}, {%0,%1,%2,%3};"
                        : "+f"(c[0]), "+f"(c[1]), "+f"(c[2]), "+f"(c[3])
                        : "r"(af[mt][0]), "r"(af[mt][1]), "r"(af[mt][2]), "r"(af[mt][3]),
                          "r"(b0), "r"(b1));
                }
        }
    }

#pragma unroll
    for (int mt = 0; mt < 2; mt++) {
        int r0 = m0 + wm * 32 + mt * 16 + g;
#pragma unroll
        for (int half = 0; half < 2; half++) {
            int row = r0 + half * 8;
            if (row >= M) continue;
#pragma unroll
            for (int nt = 0; nt < 8; nt++) {
                int col = n0 + wn * 64 + nt * 8 + 2 * tq;
                float* p = C + (size_t)row * Nc + col;
                float2 cv;
                cv.x = acc[mt][nt][half * 2 + 0];
                cv.y = acc[mt][nt][half * 2 + 1];
                if (accFlag) { float2 o = *(const float2*)p; cv.x += o.x; cv.y += o.y; }
                if (bias != nullptr) { cv.x += bias[col]; cv.y += bias[col + 1]; }
                if (reluFlag) { cv.x = fmaxf(cv.x, 0.f); cv.y = fmaxf(cv.y, 0.f); }
                if (roundFlag) { cv.x = rtf(cv.x); cv.y = rtf(cv.y); }
                *(float2*)p = cv;
            }
        }
    }
#undef ASX
#undef BSX
}

// ---------------- GAT: per-node attention logits (float4) ----------------
__global__ __launch_bounds__(256) void k_al(const float* __restrict__ aS,
                                            const float* __restrict__ aD) {
    int gw = (int)(((size_t)blockIdx.x * blockDim.x + threadIdx.x) >> 5);
    int lane = threadIdx.x & 31;
    if (gw >= NN * 2) return;
    int n = gw >> 1, k = gw & 1;
    const float4* hp = (const float4*)(g_h + (size_t)n * 512 + k * 256);
    const float4* as4 = (const float4*)(aS + k * 256);
    const float4* ad4 = (const float4*)(aD + k * 256);
    float ss = 0.f, sd = 0.f;
#pragma unroll
    for (int it = 0; it < 2; it++) {
        int j = lane + it * 32;
        float4 h = hp[j], A = as4[j], D = ad4[j];
        ss += h.x * A.x + h.y * A.y + h.z * A.z + h.w * A.w;
        sd += h.x * D.x + h.y * D.y + h.z * D.z + h.w * D.w;
    }
#pragma unroll
    for (int o = 16; o; o >>= 1) {
        ss += __shfl_down_sync(0xffffffffu, ss, o);
        sd += __shfl_down_sync(0xffffffffu, sd, o);
    }
    if (lane == 0) { g_als[gw] = ss; g_ald[gw] = sd; }
}

// ---------------- GAT: online-softmax, thread owns float2 of features ----------------
__global__ __launch_bounds__(256) void k_gat(const float* __restrict__ bias) {
    __shared__ float sW0[256], sW1[256];
    __shared__ int   sS[256];
    __shared__ float wm0[8], wm1[8];
    __shared__ float2 stage[128];
    int n = blockIdx.x;
    int t = threadIdx.x;
    int lane = t & 31, warp = t >> 5;
    int base = g_rowstart[n], deg = g_deg[n];

    float ald0 = g_ald[2 * n], ald1 = g_ald[2 * n + 1];
    float m0 = lrelu(g_als[2 * n] + ald0);
    float m1 = lrelu(g_als[2 * n + 1] + ald1);
    float d0 = 1.f, d1 = 1.f;
    const float2* h2 = (const float2*)g_h;
    float2 a = h2[(size_t)n * 256 + t];
    bool head0 = (t < 128);

    for (int c0 = 0; c0 < deg; c0 += 256) {
        int cnt = min(256, deg - c0);
        float e0 = -1e30f, e1 = -1e30f;
        int sNode = 0;
        if (t < cnt) {
            sNode = g_es[base + c0 + t];
            e0 = lrelu(g_als[2 * sNode] + ald0);
            e1 = lrelu(g_als[2 * sNode + 1] + ald1);
        }
        float w0r = e0, w1r = e1;
#pragma unroll
        for (int o = 16; o; o >>= 1) {
            w0r = fmaxf(w0r, __shfl_xor_sync(0xffffffffu, w0r, o));
            w1r = fmaxf(w1r, __shfl_xor_sync(0xffffffffu, w1r, o));
        }
        if (lane == 0) { wm0[warp] = w0r; wm1[warp] = w1r; }
        __syncthreads();
        float cm0 = wm0[0], cm1 = wm1[0];
#pragma unroll
        for (int w = 1; w < 8; w++) { cm0 = fmaxf(cm0, wm0[w]); cm1 = fmaxf(cm1, wm1[w]); }

        float M0 = fmaxf(m0, cm0), M1 = fmaxf(m1, cm1);
        float sc0 = expf(m0 - M0), sc1 = expf(m1 - M1);
        float scMe = head0 ? sc0 : sc1;
        a.x *= scMe; a.y *= scMe;
        d0 *= sc0; d1 *= sc1; m0 = M0; m1 = M1;

        if (t < cnt) {
            sS[t] = sNode;
            sW0[t] = expf(e0 - m0);
            sW1[t] = expf(e1 - m1);
        }
        __syncthreads();
        for (int j = 0; j < cnt; j++) {
            float w0 = sW0[j], w1 = sW1[j];
            float w = head0 ? w0 : w1;
            float2 hv = h2[(size_t)sS[j] * 256 + t];
            a.x += w * hv.x; a.y += w * hv.y;
            d0 += w0; d1 += w1;
        }
        __syncthreads();
    }
    float i0 = 1.f / fmaxf(d0, 1e-16f), i1 = 1.f / fmaxf(d1, 1e-16f);
    if (!head0) stage[t - 128] = a;
    __syncthreads();
    if (head0) {
        float2 b1 = stage[t];
        float v0 = 0.5f * (a.x * i0 + b1.x * i1) + bias[2 * t];
        float v1 = 0.5f * (a.y * i0 + b1.y * i1) + bias[2 * t + 1];
        float2 o;
        o.x = rtf(fmaxf(v0, 0.f));
        o.y = rtf(fmaxf(v1, 0.f));
        ((float2*)g_xgat)[(size_t)n * 128 + t] = o;
    }
}

// ---------------- RGCN gather ----------------
__global__ __launch_bounds__(128) void k_rgcn() {
    __shared__ float4 sred[4][32];
    int n = blockIdx.x;
    int t = threadIdx.x;
    int grp = t >> 5, lane = t & 31;
    int base = g_rowstart[n], deg = g_deg[n];
    float w0 = g_invcnt4[n * 4 + 0], w1 = g_invcnt4[n * 4 + 1];
    float w2 = g_invcnt4[n * 4 + 2], w3 = g_invcnt4[n * 4 + 3];
    const float4* xt4 = (const float4*)g_xt;
    float4 acc = make_float4(0.f, 0.f, 0.f, 0.f);
    for (int j = grp; j < deg; j += 4) {
        int s = g_es[base + j];
        int r = g_etl[base + j];
        float w = (r == 0) ? w0 : (r == 1) ? w1 : (r == 2) ? w2 : w3;
        float4 v = xt4[((size_t)r * NN + s) * 32 + lane];
        acc.x += w * v.x; acc.y += w * v.y; acc.z += w * v.z; acc.w += w * v.w;
    }
    sred[grp][lane] = acc;
    __syncthreads();
    if (grp == 0) {
        float4 A = sred[0][lane], B = sred[1][lane], C = sred[2][lane], D = sred[3][lane];
        float4 o;
        o.x = rtf(A.x + B.x + C.x + D.x);
        o.y = rtf(A.y + B.y + C.y + D.y);
        o.z = rtf(A.z + B.z + C.z + D.z);
        o.w = rtf(A.w + B.w + C.w + D.w);
        ((float4*)g_xrgcn)[(size_t)n * 32 + lane] = o;
    }
}

// ---------------- fold rgcn root into fusion weights ----------------
__global__ void k_compose(const float* __restrict__ fW, const float* __restrict__ fB,
                          const float* __restrict__ Wroot, const float* __restrict__ rgcB,
                          float* __restrict__ btfus) {
    int b = blockIdx.x, t = threadIdx.x;
    const float* F3 = fW + 512 * EMBD;
    if (b < HID) {
        float acc = fW[(256 + b) * EMBD + t];
        for (int h = 0; h < EMBD; h++)
            acc += Wroot[b * EMBD + h] * F3[h * EMBD + t];
        btfus[(size_t)t * 640 + 256 + b] = rtf(acc);
    } else {
        float acc = fB[t];
        for (int h = 0; h < EMBD; h++)
            acc += rgcB[h] * F3[h * EMBD + t];
        g_fb2[t] = acc;
    }
}

// ---------------- final L2 normalize ----------------
__global__ void k_norm(float* __restrict__ out) {
    int n = blockIdx.x;
    int t = threadIdx.x;
    float v = out[(size_t)n * EMBD + t];
    float s = v * v;
#pragma unroll
    for (int o = 16; o; o >>= 1) s += __shfl_down_sync(0xffffffffu, s, o);
    __shared__ float sh[4];
    if ((t & 31) == 0) sh[t >> 5] = s;
    __syncthreads();
    float tot = sh[0] + sh[1] + sh[2] + sh[3];
    float nrm = fmaxf(sqrtf(tot), 1e-12f);
    out[(size_t)n * EMBD + t] = v / nrm;
}

// ---------------- host ----------------
#define TG_SMEM (4 * 2 * 2560 * 4)

static void launch_seg(const float* A0, int K0, const float* A1, int K1,
                       const float* A2, int K2, const float* Bt,
                       float* C, const float* bias, int M, int Nc,
                       int acc, int relu, int rnd,
                       int gz = 1, size_t zsB = 0, size_t zsC = 0) {
    dim3 grid(Nc / 128, (M + 127) / 128, gz);
    tgemm<<<grid, 256, TG_SMEM>>>(A0, K0, A1, K1, A2, K2, Bt, C, bias, M, Nc,
                                  acc, relu, rnd, zsB, zsC);
}

extern "C" void kernel_launch(void* const* d_in, const int* in_sizes, int n_in,
                              void* d_out, int out_size) {
    const float* x    = (const float*)d_in[0];
    const int*   ei   = (const int*)d_in[1];
    const int*   et   = (const int*)d_in[2];
    const float* s1Wl = (const float*)d_in[3];
    const float* s1Wr = (const float*)d_in[4];
    const float* s1b  = (const float*)d_in[5];
    const float* s2Wl = (const float*)d_in[6];
    const float* s2Wr = (const float*)d_in[7];
    const float* s2b  = (const float*)d_in[8];
    const float* gatW = (const float*)d_in[9];
    const float* aSrc = (const float*)d_in[10];
    const float* aDst = (const float*)d_in[11];
    const float* gatB = (const float*)d_in[12];
    const float* Wrel = (const float*)d_in[13];
    const float* Wroot= (const float*)d_in[14];
    const float* rgcB = (const float*)d_in[15];
    const float* fW   = (const float*)d_in[16];
    const float* fB   = (const float*)d_in[17];
    float* out = (float*)d_out;

    const int* src = ei;
    const int* dst = ei + EE;

    cudaFuncSetAttribute(tgemm, cudaFuncAttributeMaxDynamicSharedMemorySize, TG_SMEM);

    float *p_xr, *p_agg1, *p_x1, *p_agg2, *p_xsage, *p_h, *p_xgat, *p_xt, *p_xrgcn, *p_fb2;
    float *p_bt1r, *p_bt1l, *p_bt2, *p_btg, *p_btrel, *p_btfus;
    cudaGetSymbolAddress((void**)&p_xr, g_xr);
    cudaGetSymbolAddress((void**)&p_agg1, g_agg1);
    cudaGetSymbolAddress((void**)&p_x1, g_x1);
    cudaGetSymbolAddress((void**)&p_agg2, g_agg2);
    cudaGetSymbolAddress((void**)&p_xsage, g_xsage);
    cudaGetSymbolAddress((void**)&p_h, g_h);
    cudaGetSymbolAddress((void**)&p_xgat, g_xgat);
    cudaGetSymbolAddress((void**)&p_xt, g_xt);
    cudaGetSymbolAddress((void**)&p_xrgcn, g_xrgcn);
    cudaGetSymbolAddress((void**)&p_fb2, g_fb2);
    cudaGetSymbolAddress((void**)&p_bt1r, g_bt1r);
    cudaGetSymbolAddress((void**)&p_bt1l, g_bt1l);
    cudaGetSymbolAddress((void**)&p_bt2, g_bt2);
    cudaGetSymbolAddress((void**)&p_btg, g_btg);
    cudaGetSymbolAddress((void**)&p_btrel, g_btrel);
    cudaGetSymbolAddress((void**)&p_btfus, g_btfus);

    // launches 1-4 (ncu profiles #4 -> a GEMM)
    k_zero_small<<<(NN * RR + 255) / 256, 256>>>();                             // 1
    k_transB<<<(128 * 256 + 255) / 256, 256>>>(s1Wr, p_bt1r, 128, 256, 128, 0); // 2
    k_round4<<<(NN * IN_C / 4 + 255) / 256, 256>>>((const float4*)x, (float4*)p_xr,
                                                   NN * IN_C / 4);              // 3
    launch_seg(p_xr, IN_C, 0, 0, 0, 0, p_bt1r, p_x1, nullptr,
               NN, HID, 0, 0, 0);                                               // 4

    // CSR build
    k_count<<<(EE + 255) / 256, 256>>>(dst, et);
    k_scan1<<<NBLK, 256>>>();
    k_scan2<<<1, 256>>>();
    k_scan3_inv<<<NBLK, 256>>>();
    k_fill<<<(EE + 255) / 256, 256>>>(src, dst, et);

    // all remaining weight transposes in ONE launch
    TSegs ts;
    ts.s[0] = {s1Wl, p_bt1l, 128, 256, 128, 0};
    ts.s[1] = {s2Wl, p_bt2, 256, 256, 512, 0};
    ts.s[2] = {s2Wr, p_bt2, 256, 256, 512, 256};
    ts.s[3] = {gatW, p_btg, 256, 512, 256, 0};
    ts.s[4] = {Wrel + 0 * (size_t)HID * EMBD, p_btrel + 0 * (size_t)128 * 256, 256, 128, 256, 0};
    ts.s[5] = {Wrel + 1 * (size_t)HID * EMBD, p_btrel + 1 * (size_t)128 * 256, 256, 128, 256, 0};
    ts.s[6] = {Wrel + 2 * (size_t)HID * EMBD, p_btrel + 2 * (size_t)128 * 256, 256, 128, 256, 0};
    ts.s[7] = {Wrel + 3 * (size_t)HID * EMBD, p_btrel + 3 * (size_t)128 * 256, 256, 128, 256, 0};
    ts.s[8] = {fW, p_btfus, 256, 128, 640, 0};
    ts.s[9] = {fW + 512 * EMBD, p_btfus, 128, 128, 640, 512};
    k_transAll<<<dim3(512, 10), 256>>>(ts);
    k_compose<<<HID + 1, EMBD>>>(fW, fB, Wroot, rgcB, p_btfus);

    // ---- SAGE 1 ----
    k_sage_gather<IN_C><<<NN, IN_C>>>(x, p_agg1);
    launch_seg(p_agg1, IN_C, 0, 0, 0, 0, p_bt1l, p_x1, s1b, NN, HID, 1, 1, 1);

    // ---- SAGE 2 ----
    k_sage_gather<HID><<<NN, HID>>>(p_x1, p_agg2);
    launch_seg(p_agg2, HID, p_x1, HID, 0, 0, p_bt2, p_xsage, s2b, NN, HID, 0, 1, 1);

    // ---- GAT ----
    launch_seg(p_xsage, HID, 0, 0, 0, 0, p_btg, p_h, nullptr, NN, 2 * HID, 0, 0, 0);
    k_al<<<(NN * 2 * 32 + 255) / 256, 256>>>(aSrc, aDst);
    k_gat<<<NN, 256>>>(gatB);

    // ---- RGCN ----
    launch_seg(p_xgat, HID, 0, 0, 0, 0, p_btrel, p_xt, nullptr, NN, EMBD, 0, 0, 0,
               RR, (size_t)128 * 256, (size_t)NN * EMBD);
    k_rgcn<<<NN, 128>>>();

    // ---- Fusion + normalize ----
    launch_seg(p_xsage, HID, p_xgat, HID, p_xrgcn, EMBD, p_btfus,
               out, p_fb2, NN, EMBD, 0, 0, 0);
    k_norm<<<NN, 128>>>(out);
}